// round 1
// baseline (speedup 1.0000x reference)
#include <cuda_runtime.h>
#include <math.h>

// Problem constants
#define HH      112
#define WW2     112
#define CC      96
#define SHIFT_  3
#define NTOK    49
#define SPAD    52        // padded i-dim of score tile (mult of 4)
#define MPAD    64        // padded token dim per window
#define QKSCALE 0.17677669529663687f   // 1/sqrt(32)
#define NWIN_TOT 16384
#define NBLK2    12544     // 802816 / 64

#define LOAD8(AV, PTR) { \
    float4 _a0 = *(const float4*)(PTR); \
    float4 _a1 = *(const float4*)((PTR)+4); \
    AV[0]=_a0.x; AV[1]=_a0.y; AV[2]=_a0.z; AV[3]=_a0.w; \
    AV[4]=_a1.x; AV[5]=_a1.y; AV[6]=_a1.z; AV[7]=_a1.w; }

#define FMA_8x4(ACC, AV, B4) \
    _Pragma("unroll") \
    for (int mi_ = 0; mi_ < 8; ++mi_) { \
        ACC[mi_*4+0] = fmaf(AV[mi_], B4.x, ACC[mi_*4+0]); \
        ACC[mi_*4+1] = fmaf(AV[mi_], B4.y, ACC[mi_*4+1]); \
        ACC[mi_*4+2] = fmaf(AV[mi_], B4.z, ACC[mi_*4+2]); \
        ACC[mi_*4+3] = fmaf(AV[mi_], B4.w, ACC[mi_*4+3]); \
    }

// ---------------------------------------------------------------------------
// Kernel 1: LN1 + shifted-window MHSA + proj + residual. One block per window.
// smem layouts (all float):
//   xlnT [96][64]  LN'd input, transposed (k-major) -- later aliased as oT[96][64]
//   qT   [96][64]  Q transposed, pre-scaled
//   kT   [96][64]  K transposed
//   vS   [64][96]  V row-major
//   sS   [3][49][SPAD] scores s[h][j][i]
//   srcI [49]      source token indices
// ---------------------------------------------------------------------------
__global__ __launch_bounds__(288, 1)
void swin_attn_kernel(const float* __restrict__ x,
                      const float* __restrict__ g1, const float* __restrict__ b1,
                      const float* __restrict__ qkv_w, const float* __restrict__ qkv_b,
                      const float* __restrict__ proj_w, const float* __restrict__ proj_b,
                      const float* __restrict__ rpb, const int* __restrict__ rel_index,
                      const float* __restrict__ attn_mask,
                      float* __restrict__ out)
{
    extern __shared__ float smem[];
    float* xlnT = smem;                   // 6144 floats (also oT)
    float* qT   = xlnT + 96*MPAD;         // 6144
    float* kT   = qT   + 96*MPAD;         // 6144
    float* vS   = kT   + 96*MPAD;         // 6144
    float* sS   = vS   + MPAD*96;         // 3*49*SPAD = 7644
    int*   srcI = (int*)(sS + 3*NTOK*SPAD);

    const int tid  = threadIdx.x;
    const int w    = blockIdx.x;
    const int bimg = w >> 8;
    const int rem  = w & 255;
    const int wh   = rem >> 4, wwc = rem & 15;

    // ---- Phase 0: LayerNorm + shifted gather (warp per token) ----
    {
        int warp = tid >> 5, lane = tid & 31;
        for (int t = warp; t < NTOK; t += 9) {
            int ii = t / 7, jj = t - ii*7;
            int oh = wh*7 + ii + SHIFT_; if (oh >= HH)  oh -= HH;
            int ow = wwc*7 + jj + SHIFT_; if (ow >= WW2) ow -= WW2;
            int src = (bimg*HH + oh)*WW2 + ow;
            if (lane == 0) srcI[t] = src;
            const float* xr = x + (size_t)src*CC;
            float v0 = xr[lane], v1 = xr[lane+32], v2 = xr[lane+64];
            float s = v0 + v1 + v2;
            #pragma unroll
            for (int o = 16; o; o >>= 1) s += __shfl_xor_sync(0xffffffffu, s, o);
            float mean = s * (1.0f/96.0f);
            float d0 = v0-mean, d1 = v1-mean, d2 = v2-mean;
            float q2 = d0*d0 + d1*d1 + d2*d2;
            #pragma unroll
            for (int o = 16; o; o >>= 1) q2 += __shfl_xor_sync(0xffffffffu, q2, o);
            float rstd = rsqrtf(q2*(1.0f/96.0f) + 1e-5f);
            xlnT[lane*MPAD + t]      = d0*rstd*g1[lane]    + b1[lane];
            xlnT[(lane+32)*MPAD + t] = d1*rstd*g1[lane+32] + b1[lane+32];
            xlnT[(lane+64)*MPAD + t] = d2*rstd*g1[lane+64] + b1[lane+64];
        }
        // zero pad columns 49..63
        for (int idx = tid; idx < 96*(MPAD-NTOK); idx += 288) {
            int k = idx / (MPAD-NTOK);
            int t = NTOK + (idx - k*(MPAD-NTOK));
            xlnT[k*MPAD + t] = 0.0f;
        }
    }
    __syncthreads();

    // ---- Phase 1: QKV GEMM [64 x 288] = xln(64x96) @ qkv_w(96x288) ----
    // Each thread owns two 8x4 tiles (same cols, token groups mg and mg+4).
    {
        int ng  = tid % 72;
        int mgA = tid / 72;                 // 0..3
        int c0  = ng*4;
        int t0a = mgA*8, t0b = t0a + 32;
        float acc0[32], acc1[32];
        #pragma unroll
        for (int i = 0; i < 32; ++i) { acc0[i] = 0.f; acc1[i] = 0.f; }
        const float* Bp = qkv_w + c0;
        #pragma unroll 4
        for (int k = 0; k < 96; ++k) {
            float4 B4 = *(const float4*)(Bp + k*288);
            float av0[8], av1[8];
            LOAD8(av0, xlnT + k*MPAD + t0a);
            LOAD8(av1, xlnT + k*MPAD + t0b);
            FMA_8x4(acc0, av0, B4);
            FMA_8x4(acc1, av1, B4);
        }
        int sel = c0 / 96;                  // 0=q, 1=k, 2=v (uniform over 4 cols)
        int ccb = c0 - sel*96;
        float bi[4];
        #pragma unroll
        for (int ni = 0; ni < 4; ++ni) bi[ni] = qkv_b[c0+ni];
        #pragma unroll
        for (int p = 0; p < 2; ++p) {
            int t0 = p ? t0b : t0a;
            const float* acc = p ? acc1 : acc0;
            #pragma unroll
            for (int mi = 0; mi < 8; ++mi) {
                int t = t0 + mi;
                #pragma unroll
                for (int ni = 0; ni < 4; ++ni) {
                    float val = acc[mi*4+ni] + bi[ni];
                    int cc = ccb + ni;
                    if (sel == 0)      qT[cc*MPAD + t] = val * QKSCALE;
                    else if (sel == 1) kT[cc*MPAD + t] = val;
                    else               vS[t*96 + cc]   = val;
                }
            }
        }
    }
    __syncthreads();

    // ---- Phase 2: scores s[h][j][i] = (Kj . Qi) + bias + mask ----
    // tiles: 3 heads x 7 j-groups(8) x 13 i-groups(4) = 273 tiles
    if (tid < 273) {
        int ng = tid % 13, rest = tid / 13;
        int mg = rest % 7, h = rest / 7;
        int i0 = ng*4, j0 = mg*8;
        const float* qb = qT + (h*32)*MPAD;
        const float* kb = kT + (h*32)*MPAD;
        float acc[32];
        #pragma unroll
        for (int i = 0; i < 32; ++i) acc[i] = 0.f;
        #pragma unroll 4
        for (int d = 0; d < 32; ++d) {
            float4 q4 = *(const float4*)(qb + d*MPAD + i0);
            float kv[8];
            LOAD8(kv, kb + d*MPAD + j0);
            FMA_8x4(acc, kv, q4);
        }
        const float* mbase = attn_mask + (size_t)rem*2401;
        #pragma unroll
        for (int mi = 0; mi < 8; ++mi) {
            int j = j0 + mi;
            if (j < NTOK) {
                #pragma unroll
                for (int ni = 0; ni < 4; ++ni) {
                    int i = i0 + ni;
                    float val = acc[mi*4+ni];
                    if (i < NTOK) {
                        int ridx = rel_index[i*NTOK + j];
                        val += rpb[ridx*3 + h] + mbase[i*NTOK + j];
                    }
                    sS[(h*NTOK + j)*SPAD + i] = val;
                }
            }
        }
    }
    __syncthreads();

    // ---- Phase 3: softmax over j for each (h, i) -- warp per row ----
    {
        int warp = tid >> 5, lane = tid & 31;
        for (int row = warp; row < 3*NTOK; row += 9) {
            int h = row / NTOK, i = row - h*NTOK;
            float* sp = sS + h*NTOK*SPAD + i;
            float e0 = (lane < NTOK)      ? sp[lane*SPAD]      : -1e30f;
            float e1 = (lane + 32 < NTOK) ? sp[(lane+32)*SPAD] : -1e30f;
            float m = fmaxf(e0, e1);
            #pragma unroll
            for (int o = 16; o; o >>= 1) m = fmaxf(m, __shfl_xor_sync(0xffffffffu, m, o));
            e0 = (lane < NTOK)      ? __expf(e0 - m) : 0.f;
            e1 = (lane + 32 < NTOK) ? __expf(e1 - m) : 0.f;
            float s = e0 + e1;
            #pragma unroll
            for (int o = 16; o; o >>= 1) s += __shfl_xor_sync(0xffffffffu, s, o);
            float inv = 1.0f / s;
            if (lane < NTOK)      sp[lane*SPAD]      = e0 * inv;
            if (lane + 32 < NTOK) sp[(lane+32)*SPAD] = e1 * inv;
        }
    }
    __syncthreads();

    // ---- Phase 4: A.V -> oT[c][i] (oT aliases xlnT) ----
    // tiles: 12 c-groups(8) x 13 i-groups(4) = 156
    if (tid < 156) {
        int ng = tid % 13, mg = tid / 13;
        int i0 = ng*4, c0 = mg*8;
        int h = c0 >> 5;
        const float* sb = sS + h*NTOK*SPAD;
        float acc[32];
        #pragma unroll
        for (int i = 0; i < 32; ++i) acc[i] = 0.f;
        #pragma unroll 2
        for (int j = 0; j < NTOK; ++j) {
            float4 s4 = *(const float4*)(sb + j*SPAD + i0);
            float vv[8];
            LOAD8(vv, vS + j*96 + c0);
            FMA_8x4(acc, vv, s4);
        }
        float* oT = xlnT;
        #pragma unroll
        for (int mi = 0; mi < 8; ++mi)
            #pragma unroll
            for (int ni = 0; ni < 4; ++ni)
                oT[(c0+mi)*MPAD + (i0+ni)] = acc[mi*4+ni];
    }
    __syncthreads();

    // ---- Phase 5: proj + residual, scatter to output ----
    // tiles: 7 i-groups(8) x 24 c-groups(4) = 168
    if (tid < 168) {
        int ng = tid % 24, mg = tid / 24;
        int c0 = ng*4, i0 = mg*8;
        const float* oT = xlnT;
        float acc[32];
        #pragma unroll
        for (int i = 0; i < 32; ++i) acc[i] = 0.f;
        #pragma unroll 4
        for (int k = 0; k < 96; ++k) {
            float4 B4 = *(const float4*)(proj_w + k*96 + c0);
            float av[8];
            LOAD8(av, oT + k*MPAD + i0);
            FMA_8x4(acc, av, B4);
        }
        float4 pb = *(const float4*)(proj_b + c0);
        #pragma unroll
        for (int mi = 0; mi < 8; ++mi) {
            int i = i0 + mi;
            if (i < NTOK) {
                size_t base = (size_t)srcI[i]*96 + c0;
                float4 xr = *(const float4*)(x + base);
                float4 r;
                r.x = acc[mi*4+0] + pb.x + xr.x;
                r.y = acc[mi*4+1] + pb.y + xr.y;
                r.z = acc[mi*4+2] + pb.z + xr.z;
                r.w = acc[mi*4+3] + pb.w + xr.w;
                *(float4*)(out + base) = r;
            }
        }
    }
}

// ---------------------------------------------------------------------------
// Kernel 2: LN2 + MLP (fc1 -> exact GELU -> fc2) + residual. In-place on xio.
// 64 tokens / block, 384 threads.
// smem: xlnT [96][64] (later: k-split partial buffer), hT [384][64]
// ---------------------------------------------------------------------------
__global__ __launch_bounds__(384, 1)
void swin_mlp_kernel(const float* __restrict__ g2, const float* __restrict__ b2,
                     const float* __restrict__ fc1_w, const float* __restrict__ fc1_b,
                     const float* __restrict__ fc2_w, const float* __restrict__ fc2_b,
                     float* __restrict__ xio)
{
    extern __shared__ float smem[];
    float* xlnT = smem;            // 96*64 = 6144 floats
    float* hT   = smem + 96*64;    // 384*64 = 24576 floats

    const int tid  = threadIdx.x;
    const int tok0 = blockIdx.x * 64;

    // ---- LN2 ----
    {
        int warp = tid >> 5, lane = tid & 31;
        for (int t = warp; t < 64; t += 12) {
            const float* xr = xio + (size_t)(tok0+t)*96;
            float v0 = xr[lane], v1 = xr[lane+32], v2 = xr[lane+64];
            float s = v0 + v1 + v2;
            #pragma unroll
            for (int o = 16; o; o >>= 1) s += __shfl_xor_sync(0xffffffffu, s, o);
            float mean = s * (1.0f/96.0f);
            float d0 = v0-mean, d1 = v1-mean, d2 = v2-mean;
            float q2 = d0*d0 + d1*d1 + d2*d2;
            #pragma unroll
            for (int o = 16; o; o >>= 1) q2 += __shfl_xor_sync(0xffffffffu, q2, o);
            float rstd = rsqrtf(q2*(1.0f/96.0f) + 1e-5f);
            xlnT[lane*64 + t]      = d0*rstd*g2[lane]    + b2[lane];
            xlnT[(lane+32)*64 + t] = d1*rstd*g2[lane+32] + b2[lane+32];
            xlnT[(lane+64)*64 + t] = d2*rstd*g2[lane+64] + b2[lane+64];
        }
    }
    __syncthreads();

    // ---- GEMM1 + exact GELU: hT[c][t] = gelu(xln @ fc1_w + fc1_b) ----
    // thread owns 2 tiles (8 tok x 4 col): (mg, ng) and (mg+4, ng)
    {
        int ng  = tid % 96;
        int mgA = tid / 96;                 // 0..3
        int c0  = ng*4;
        int t0a = mgA*8, t0b = t0a + 32;
        float acc0[32], acc1[32];
        #pragma unroll
        for (int i = 0; i < 32; ++i) { acc0[i] = 0.f; acc1[i] = 0.f; }
        const float* Bp = fc1_w + c0;
        #pragma unroll 4
        for (int k = 0; k < 96; ++k) {
            float4 B4 = *(const float4*)(Bp + k*384);
            float av0[8], av1[8];
            LOAD8(av0, xlnT + k*64 + t0a);
            LOAD8(av1, xlnT + k*64 + t0b);
            FMA_8x4(acc0, av0, B4);
            FMA_8x4(acc1, av1, B4);
        }
        float4 bb = *(const float4*)(fc1_b + c0);
        float bi[4] = {bb.x, bb.y, bb.z, bb.w};
        #pragma unroll
        for (int p = 0; p < 2; ++p) {
            int t0 = p ? t0b : t0a;
            const float* acc = p ? acc1 : acc0;
            #pragma unroll
            for (int mi = 0; mi < 8; ++mi)
                #pragma unroll
                for (int ni = 0; ni < 4; ++ni) {
                    float v = acc[mi*4+ni] + bi[ni];
                    float g = 0.5f * v * (1.0f + erff(v * 0.7071067811865476f));
                    hT[(c0+ni)*64 + (t0+mi)] = g;
                }
        }
    }
    __syncthreads();

    // ---- GEMM2 (k = 384, split in 2) + bias + residual ----
    // 192 tiles (8 tok x 4 col); thread = (tile, k-half)
    {
        int tile = tid % 192, kh = tid / 192;
        int ng = tile % 24, mg = tile / 24;
        int c0 = ng*4, t0 = mg*8;
        float acc[32];
        #pragma unroll
        for (int i = 0; i < 32; ++i) acc[i] = 0.f;
        int kbeg = kh*192;
        const float* Bp = fc2_w + c0;
        #pragma unroll 4
        for (int k = kbeg; k < kbeg + 192; ++k) {
            float4 B4 = *(const float4*)(Bp + k*96);
            float av[8];
            LOAD8(av, hT + k*64 + t0);
            FMA_8x4(acc, av, B4);
        }
        float* pbuf = xlnT;   // dead after GEMM1; 192*32 = 6144 floats exactly
        if (kh == 1) {
            #pragma unroll
            for (int i = 0; i < 32; ++i) pbuf[tile*32 + i] = acc[i];
        }
        __syncthreads();
        if (kh == 0) {
            #pragma unroll
            for (int i = 0; i < 32; ++i) acc[i] += pbuf[tile*32 + i];
            float4 bb = *(const float4*)(fc2_b + c0);
            #pragma unroll
            for (int mi = 0; mi < 8; ++mi) {
                size_t base = (size_t)(tok0 + t0 + mi)*96 + c0;
                float4 sk = *(const float4*)(xio + base);
                float4 r;
                r.x = acc[mi*4+0] + bb.x + sk.x;
                r.y = acc[mi*4+1] + bb.y + sk.y;
                r.z = acc[mi*4+2] + bb.z + sk.z;
                r.w = acc[mi*4+3] + bb.w + sk.w;
                *(float4*)(xio + base) = r;
            }
        }
    }
}

// ---------------------------------------------------------------------------
extern "C" void kernel_launch(void* const* d_in, const int* in_sizes, int n_in,
                              void* d_out, int out_size)
{
    const float* x      = (const float*)d_in[0];
    const float* g1     = (const float*)d_in[1];
    const float* b1     = (const float*)d_in[2];
    const float* qkv_w  = (const float*)d_in[3];
    const float* qkv_b  = (const float*)d_in[4];
    const float* proj_w = (const float*)d_in[5];
    const float* proj_b = (const float*)d_in[6];
    const float* rpb    = (const float*)d_in[7];
    const float* g2     = (const float*)d_in[8];
    const float* b2     = (const float*)d_in[9];
    const float* fc1_w  = (const float*)d_in[10];
    const float* fc1_b  = (const float*)d_in[11];
    const float* fc2_w  = (const float*)d_in[12];
    const float* fc2_b  = (const float*)d_in[13];
    const int*   relidx = (const int*)d_in[14];
    const float* amask  = (const float*)d_in[15];
    float* out = (float*)d_out;

    const int smem1 = (4*96*MPAD + 3*NTOK*SPAD)*(int)sizeof(float) + NTOK*(int)sizeof(int);
    const int smem2 = (96*64 + 384*64)*(int)sizeof(float);
    cudaFuncSetAttribute(swin_attn_kernel, cudaFuncAttributeMaxDynamicSharedMemorySize, smem1);
    cudaFuncSetAttribute(swin_mlp_kernel,  cudaFuncAttributeMaxDynamicSharedMemorySize, smem2);

    swin_attn_kernel<<<NWIN_TOT, 288, smem1>>>(x, g1, b1, qkv_w, qkv_b, proj_w, proj_b,
                                               rpb, relidx, amask, out);
    swin_mlp_kernel<<<NBLK2, 384, smem2>>>(g2, b2, fc1_w, fc1_b, fc2_w, fc2_b, out);
}

// round 2
// speedup vs baseline: 1.5282x; 1.5282x over previous
#include <cuda_runtime.h>
#include <cuda_bf16.h>
#include <math.h>
#include <stdint.h>

// Problem constants
#define HH      112
#define WW2     112
#define CC      96
#define SHIFT_  3
#define NTOK    49
#define SPAD    52
#define MPAD    64
#define QKSCALE 0.17677669529663687f
#define NWIN_TOT 16384
#define NBLK2    12544     // 802816 / 64

#define LOAD8(AV, PTR) { \
    float4 _a0 = *(const float4*)(PTR); \
    float4 _a1 = *(const float4*)((PTR)+4); \
    AV[0]=_a0.x; AV[1]=_a0.y; AV[2]=_a0.z; AV[3]=_a0.w; \
    AV[4]=_a1.x; AV[5]=_a1.y; AV[6]=_a1.z; AV[7]=_a1.w; }

#define FMA_8x4(ACC, AV, B4) \
    _Pragma("unroll") \
    for (int mi_ = 0; mi_ < 8; ++mi_) { \
        ACC[mi_*4+0] = fmaf(AV[mi_], B4.x, ACC[mi_*4+0]); \
        ACC[mi_*4+1] = fmaf(AV[mi_], B4.y, ACC[mi_*4+1]); \
        ACC[mi_*4+2] = fmaf(AV[mi_], B4.z, ACC[mi_*4+2]); \
        ACC[mi_*4+3] = fmaf(AV[mi_], B4.w, ACC[mi_*4+3]); \
    }

// ===========================================================================
// bf16 split-MMA helpers
// ===========================================================================
__device__ __forceinline__ void mma16816(float d[4], const uint32_t a[4],
                                         uint32_t b0, uint32_t b1) {
    asm volatile(
        "mma.sync.aligned.m16n8k16.row.col.f32.bf16.bf16.f32 "
        "{%0,%1,%2,%3},{%4,%5,%6,%7},{%8,%9},{%0,%1,%2,%3};"
        : "+f"(d[0]), "+f"(d[1]), "+f"(d[2]), "+f"(d[3])
        : "r"(a[0]), "r"(a[1]), "r"(a[2]), "r"(a[3]), "r"(b0), "r"(b1));
}

// pack two fp32 (x0 -> low half, x1 -> high half) into bf16x2 hi + residual lo
__device__ __forceinline__ void split2(float x0, float x1,
                                       uint32_t& hi, uint32_t& lo) {
    uint32_t hp;
    asm("cvt.rn.bf16x2.f32 %0, %1, %2;" : "=r"(hp) : "f"(x1), "f"(x0));
    __nv_bfloat162 hb = *reinterpret_cast<__nv_bfloat162*>(&hp);
    float l0 = x0 - __bfloat162float(hb.x);
    float l1 = x1 - __bfloat162float(hb.y);
    uint32_t lp;
    asm("cvt.rn.bf16x2.f32 %0, %1, %2;" : "=r"(lp) : "f"(l1), "f"(l0));
    hi = hp; lo = lp;
}

__device__ __forceinline__ float gelu_exact(float v) {
    return 0.5f * v * (1.0f + erff(v * 0.7071067811865476f));
}

// Pre-packed MLP weights in B-fragment order: [k16step][n][pair 0..7] bf16x2
__device__ uint32_t g_W1hi[6 * 384 * 8];
__device__ uint32_t g_W1lo[6 * 384 * 8];
__device__ uint32_t g_W2hi[24 * 96 * 8];
__device__ uint32_t g_W2lo[24 * 96 * 8];

__global__ void pack_mlp_weights(const float* __restrict__ fc1_w,
                                 const float* __restrict__ fc2_w) {
    int idx = blockIdx.x * 256 + threadIdx.x;
    if (idx >= 6 * 384 * 8) return;
    {   // fc1: 96 x 384  ->  [s<6][n<384][p<8]
        int p = idx & 7;
        int n = (idx >> 3) % 384;
        int s = idx / (384 * 8);
        int k = s * 16 + 2 * p;
        float w0 = fc1_w[k * 384 + n];
        float w1 = fc1_w[(k + 1) * 384 + n];
        uint32_t hi, lo; split2(w0, w1, hi, lo);
        g_W1hi[idx] = hi; g_W1lo[idx] = lo;
    }
    if (idx < 24 * 96 * 8) {   // fc2: 384 x 96 -> [s<24][n<96][p<8]
        int p = idx & 7;
        int n = (idx >> 3) % 96;
        int s = idx / (96 * 8);
        int k = s * 16 + 2 * p;
        float w0 = fc2_w[k * 96 + n];
        float w1 = fc2_w[(k + 1) * 96 + n];
        uint32_t hi, lo; split2(w0, w1, hi, lo);
        g_W2hi[idx] = hi; g_W2lo[idx] = lo;
    }
}

// ---------------------------------------------------------------------------
// Kernel 1: LN1 + shifted-window MHSA + proj + residual (unchanged from R1)
// ---------------------------------------------------------------------------
__global__ __launch_bounds__(288, 1)
void swin_attn_kernel(const float* __restrict__ x,
                      const float* __restrict__ g1, const float* __restrict__ b1,
                      const float* __restrict__ qkv_w, const float* __restrict__ qkv_b,
                      const float* __restrict__ proj_w, const float* __restrict__ proj_b,
                      const float* __restrict__ rpb, const int* __restrict__ rel_index,
                      const float* __restrict__ attn_mask,
                      float* __restrict__ out)
{
    extern __shared__ float smem[];
    float* xlnT = smem;
    float* qT   = xlnT + 96*MPAD;
    float* kT   = qT   + 96*MPAD;
    float* vS   = kT   + 96*MPAD;
    float* sS   = vS   + MPAD*96;
    int*   srcI = (int*)(sS + 3*NTOK*SPAD);

    const int tid  = threadIdx.x;
    const int w    = blockIdx.x;
    const int bimg = w >> 8;
    const int rem  = w & 255;
    const int wh   = rem >> 4, wwc = rem & 15;

    {
        int warp = tid >> 5, lane = tid & 31;
        for (int t = warp; t < NTOK; t += 9) {
            int ii = t / 7, jj = t - ii*7;
            int oh = wh*7 + ii + SHIFT_; if (oh >= HH)  oh -= HH;
            int ow = wwc*7 + jj + SHIFT_; if (ow >= WW2) ow -= WW2;
            int src = (bimg*HH + oh)*WW2 + ow;
            if (lane == 0) srcI[t] = src;
            const float* xr = x + (size_t)src*CC;
            float v0 = xr[lane], v1 = xr[lane+32], v2 = xr[lane+64];
            float s = v0 + v1 + v2;
            #pragma unroll
            for (int o = 16; o; o >>= 1) s += __shfl_xor_sync(0xffffffffu, s, o);
            float mean = s * (1.0f/96.0f);
            float d0 = v0-mean, d1 = v1-mean, d2 = v2-mean;
            float q2 = d0*d0 + d1*d1 + d2*d2;
            #pragma unroll
            for (int o = 16; o; o >>= 1) q2 += __shfl_xor_sync(0xffffffffu, q2, o);
            float rstd = rsqrtf(q2*(1.0f/96.0f) + 1e-5f);
            xlnT[lane*MPAD + t]      = d0*rstd*g1[lane]    + b1[lane];
            xlnT[(lane+32)*MPAD + t] = d1*rstd*g1[lane+32] + b1[lane+32];
            xlnT[(lane+64)*MPAD + t] = d2*rstd*g1[lane+64] + b1[lane+64];
        }
        for (int idx = tid; idx < 96*(MPAD-NTOK); idx += 288) {
            int k = idx / (MPAD-NTOK);
            int t = NTOK + (idx - k*(MPAD-NTOK));
            xlnT[k*MPAD + t] = 0.0f;
        }
    }
    __syncthreads();

    {
        int ng  = tid % 72;
        int mgA = tid / 72;
        int c0  = ng*4;
        int t0a = mgA*8, t0b = t0a + 32;
        float acc0[32], acc1[32];
        #pragma unroll
        for (int i = 0; i < 32; ++i) { acc0[i] = 0.f; acc1[i] = 0.f; }
        const float* Bp = qkv_w + c0;
        #pragma unroll 4
        for (int k = 0; k < 96; ++k) {
            float4 B4 = *(const float4*)(Bp + k*288);
            float av0[8], av1[8];
            LOAD8(av0, xlnT + k*MPAD + t0a);
            LOAD8(av1, xlnT + k*MPAD + t0b);
            FMA_8x4(acc0, av0, B4);
            FMA_8x4(acc1, av1, B4);
        }
        int sel = c0 / 96;
        int ccb = c0 - sel*96;
        float bi[4];
        #pragma unroll
        for (int ni = 0; ni < 4; ++ni) bi[ni] = qkv_b[c0+ni];
        #pragma unroll
        for (int p = 0; p < 2; ++p) {
            int t0 = p ? t0b : t0a;
            const float* acc = p ? acc1 : acc0;
            #pragma unroll
            for (int mi = 0; mi < 8; ++mi) {
                int t = t0 + mi;
                #pragma unroll
                for (int ni = 0; ni < 4; ++ni) {
                    float val = acc[mi*4+ni] + bi[ni];
                    int cc = ccb + ni;
                    if (sel == 0)      qT[cc*MPAD + t] = val * QKSCALE;
                    else if (sel == 1) kT[cc*MPAD + t] = val;
                    else               vS[t*96 + cc]   = val;
                }
            }
        }
    }
    __syncthreads();

    if (tid < 273) {
        int ng = tid % 13, rest = tid / 13;
        int mg = rest % 7, h = rest / 7;
        int i0 = ng*4, j0 = mg*8;
        const float* qb = qT + (h*32)*MPAD;
        const float* kb = kT + (h*32)*MPAD;
        float acc[32];
        #pragma unroll
        for (int i = 0; i < 32; ++i) acc[i] = 0.f;
        #pragma unroll 4
        for (int d = 0; d < 32; ++d) {
            float4 q4 = *(const float4*)(qb + d*MPAD + i0);
            float kv[8];
            LOAD8(kv, kb + d*MPAD + j0);
            FMA_8x4(acc, kv, q4);
        }
        const float* mbase = attn_mask + (size_t)rem*2401;
        #pragma unroll
        for (int mi = 0; mi < 8; ++mi) {
            int j = j0 + mi;
            if (j < NTOK) {
                #pragma unroll
                for (int ni = 0; ni < 4; ++ni) {
                    int i = i0 + ni;
                    float val = acc[mi*4+ni];
                    if (i < NTOK) {
                        int ridx = rel_index[i*NTOK + j];
                        val += rpb[ridx*3 + h] + mbase[i*NTOK + j];
                    }
                    sS[(h*NTOK + j)*SPAD + i] = val;
                }
            }
        }
    }
    __syncthreads();

    {
        int warp = tid >> 5, lane = tid & 31;
        for (int row = warp; row < 3*NTOK; row += 9) {
            int h = row / NTOK, i = row - h*NTOK;
            float* sp = sS + h*NTOK*SPAD + i;
            float e0 = (lane < NTOK)      ? sp[lane*SPAD]      : -1e30f;
            float e1 = (lane + 32 < NTOK) ? sp[(lane+32)*SPAD] : -1e30f;
            float m = fmaxf(e0, e1);
            #pragma unroll
            for (int o = 16; o; o >>= 1) m = fmaxf(m, __shfl_xor_sync(0xffffffffu, m, o));
            e0 = (lane < NTOK)      ? __expf(e0 - m) : 0.f;
            e1 = (lane + 32 < NTOK) ? __expf(e1 - m) : 0.f;
            float s = e0 + e1;
            #pragma unroll
            for (int o = 16; o; o >>= 1) s += __shfl_xor_sync(0xffffffffu, s, o);
            float inv = 1.0f / s;
            if (lane < NTOK)      sp[lane*SPAD]      = e0 * inv;
            if (lane + 32 < NTOK) sp[(lane+32)*SPAD] = e1 * inv;
        }
    }
    __syncthreads();

    if (tid < 156) {
        int ng = tid % 13, mg = tid / 13;
        int i0 = ng*4, c0 = mg*8;
        int h = c0 >> 5;
        const float* sb = sS + h*NTOK*SPAD;
        float acc[32];
        #pragma unroll
        for (int i = 0; i < 32; ++i) acc[i] = 0.f;
        #pragma unroll 2
        for (int j = 0; j < NTOK; ++j) {
            float4 s4 = *(const float4*)(sb + j*SPAD + i0);
            float vv[8];
            LOAD8(vv, vS + j*96 + c0);
            FMA_8x4(acc, vv, s4);
        }
        float* oT = xlnT;
        #pragma unroll
        for (int mi = 0; mi < 8; ++mi)
            #pragma unroll
            for (int ni = 0; ni < 4; ++ni)
                oT[(c0+mi)*MPAD + (i0+ni)] = acc[mi*4+ni];
    }
    __syncthreads();

    if (tid < 168) {
        int ng = tid % 24, mg = tid / 24;
        int c0 = ng*4, i0 = mg*8;
        const float* oT = xlnT;
        float acc[32];
        #pragma unroll
        for (int i = 0; i < 32; ++i) acc[i] = 0.f;
        #pragma unroll 4
        for (int k = 0; k < 96; ++k) {
            float4 B4 = *(const float4*)(proj_w + k*96 + c0);
            float av[8];
            LOAD8(av, oT + k*MPAD + i0);
            FMA_8x4(acc, av, B4);
        }
        float4 pb = *(const float4*)(proj_b + c0);
        #pragma unroll
        for (int mi = 0; mi < 8; ++mi) {
            int i = i0 + mi;
            if (i < NTOK) {
                size_t base = (size_t)srcI[i]*96 + c0;
                float4 xr = *(const float4*)(x + base);
                float4 r;
                r.x = acc[mi*4+0] + pb.x + xr.x;
                r.y = acc[mi*4+1] + pb.y + xr.y;
                r.z = acc[mi*4+2] + pb.z + xr.z;
                r.w = acc[mi*4+3] + pb.w + xr.w;
                *(float4*)(out + base) = r;
            }
        }
    }
}

// ---------------------------------------------------------------------------
// Kernel 2 (v2): LN2 + MLP via bf16 split tensor-core MMA. 64 tokens/block,
// 256 threads (8 warps). Hidden processed in 3 chunks of 128; GEMM2 result
// accumulated in persistent registers.
//   GEMM1 warps: 2M x 4N -> warp tile 32 tok x 32 hid  (2 Mt x 4 Nt)
//   GEMM2 warps: 4M x 2N -> warp tile 16 tok x 48 out  (1 Mt x 6 Nt)
// smem: xhi/xlo [64][104] bf16, hhi/hlo [64][136] bf16 = 60 KB -> 2 blocks/SM
// ---------------------------------------------------------------------------
#define XLDA 104
#define HLDA 136

__global__ __launch_bounds__(256, 2)
void swin_mlp_mma(const float* __restrict__ g2, const float* __restrict__ b2,
                  const float* __restrict__ fc1_b, const float* __restrict__ fc2_b,
                  float* __restrict__ xio)
{
    extern __shared__ char smem_raw[];
    __nv_bfloat16* xhi = (__nv_bfloat16*)smem_raw;
    __nv_bfloat16* xlo = xhi + 64*XLDA;
    __nv_bfloat16* hhi = xlo + 64*XLDA;
    __nv_bfloat16* hlo = hhi + 64*HLDA;
    uint32_t* xhi32 = (uint32_t*)xhi;
    uint32_t* xlo32 = (uint32_t*)xlo;
    uint32_t* hhi32 = (uint32_t*)hhi;
    uint32_t* hlo32 = (uint32_t*)hlo;

    const int tid   = threadIdx.x;
    const int warp  = tid >> 5, lane = tid & 31;
    const int tok0  = blockIdx.x * 64;
    const int r     = lane >> 2;          // fragment row
    const int c2    = (lane & 3) * 2;     // fragment k/col pair base
    const int q     = lane & 3;           // B pair selector
    const int nlane = lane >> 2;          // B n within tile

    // ---- LN2 -> bf16 hi/lo A matrix in smem ----
    {
        float ga = g2[lane], gb = g2[lane+32], gc = g2[lane+64];
        float ba = b2[lane], bb = b2[lane+32], bc = b2[lane+64];
        for (int t = warp; t < 64; t += 8) {
            const float* xr = xio + (size_t)(tok0+t)*96;
            float v0 = xr[lane], v1 = xr[lane+32], v2 = xr[lane+64];
            float s = v0 + v1 + v2;
            #pragma unroll
            for (int o = 16; o; o >>= 1) s += __shfl_xor_sync(0xffffffffu, s, o);
            float mean = s * (1.0f/96.0f);
            float d0 = v0-mean, d1 = v1-mean, d2 = v2-mean;
            float q2 = d0*d0 + d1*d1 + d2*d2;
            #pragma unroll
            for (int o = 16; o; o >>= 1) q2 += __shfl_xor_sync(0xffffffffu, q2, o);
            float rstd = rsqrtf(q2*(1.0f/96.0f) + 1e-5f);
            float y0 = d0*rstd*ga + ba;
            float y1 = d1*rstd*gb + bb;
            float y2 = d2*rstd*gc + bc;
            __nv_bfloat16 h0 = __float2bfloat16_rn(y0);
            __nv_bfloat16 h1 = __float2bfloat16_rn(y1);
            __nv_bfloat16 h2 = __float2bfloat16_rn(y2);
            xhi[t*XLDA + lane]      = h0;
            xhi[t*XLDA + lane + 32] = h1;
            xhi[t*XLDA + lane + 64] = h2;
            xlo[t*XLDA + lane]      = __float2bfloat16_rn(y0 - __bfloat162float(h0));
            xlo[t*XLDA + lane + 32] = __float2bfloat16_rn(y1 - __bfloat162float(h1));
            xlo[t*XLDA + lane + 64] = __float2bfloat16_rn(y2 - __bfloat162float(h2));
        }
    }
    __syncthreads();

    float acc2[6][4];
    #pragma unroll
    for (int i = 0; i < 6; ++i)
        #pragma unroll
        for (int j = 0; j < 4; ++j) acc2[i][j] = 0.f;

    const int wm1 = warp >> 2, wn1 = warp & 3;   // GEMM1 warp coords
    const int wm2 = warp >> 1, wn2 = warp & 1;   // GEMM2 warp coords

    for (int ch = 0; ch < 3; ++ch) {
        // ---- GEMM1: [64 x 128 chunk] = x(64x96) @ W1[:, chunk] ----
        float acc1[2][4][4];
        #pragma unroll
        for (int a = 0; a < 2; ++a)
            #pragma unroll
            for (int b = 0; b < 4; ++b)
                #pragma unroll
                for (int c = 0; c < 4; ++c) acc1[a][b][c] = 0.f;

        #pragma unroll
        for (int s = 0; s < 6; ++s) {
            const int k0 = s*16;
            uint32_t ah[2][4], al[2][4];
            #pragma unroll
            for (int mt = 0; mt < 2; ++mt) {
                int row  = wm1*32 + mt*16 + r;
                int base = row*XLDA + k0 + c2;
                ah[mt][0] = xhi32[base >> 1];
                ah[mt][1] = xhi32[(base + 8*XLDA) >> 1];
                ah[mt][2] = xhi32[(base + 8) >> 1];
                ah[mt][3] = xhi32[(base + 8*XLDA + 8) >> 1];
                al[mt][0] = xlo32[base >> 1];
                al[mt][1] = xlo32[(base + 8*XLDA) >> 1];
                al[mt][2] = xlo32[(base + 8) >> 1];
                al[mt][3] = xlo32[(base + 8*XLDA + 8) >> 1];
            }
            #pragma unroll
            for (int nt = 0; nt < 4; ++nt) {
                int n = ch*128 + wn1*32 + nt*8 + nlane;
                const uint32_t* bph = g_W1hi + ((size_t)s*384 + n)*8;
                const uint32_t* bpl = g_W1lo + ((size_t)s*384 + n)*8;
                uint32_t bh0 = bph[q],   bh1 = bph[4+q];
                uint32_t bl0 = bpl[q],   bl1 = bpl[4+q];
                #pragma unroll
                for (int mt = 0; mt < 2; ++mt) {
                    mma16816(acc1[mt][nt], ah[mt], bh0, bh1);
                    mma16816(acc1[mt][nt], ah[mt], bl0, bl1);
                    mma16816(acc1[mt][nt], al[mt], bh0, bh1);
                }
            }
        }

        __syncthreads();   // previous chunk's GEMM2 reads of h are done

        // ---- bias + exact GELU + bf16 split -> h smem ----
        #pragma unroll
        for (int mt = 0; mt < 2; ++mt) {
            int row0 = wm1*32 + mt*16 + r;
            #pragma unroll
            for (int nt = 0; nt < 4; ++nt) {
                int cc = wn1*32 + nt*8 + c2;
                float2 bia = *(const float2*)(fc1_b + ch*128 + cc);
                float g00 = gelu_exact(acc1[mt][nt][0] + bia.x);
                float g01 = gelu_exact(acc1[mt][nt][1] + bia.y);
                uint32_t hp, lp;
                split2(g00, g01, hp, lp);
                hhi32[(row0*HLDA + cc) >> 1] = hp;
                hlo32[(row0*HLDA + cc) >> 1] = lp;
                float g10 = gelu_exact(acc1[mt][nt][2] + bia.x);
                float g11 = gelu_exact(acc1[mt][nt][3] + bia.y);
                split2(g10, g11, hp, lp);
                hhi32[((row0+8)*HLDA + cc) >> 1] = hp;
                hlo32[((row0+8)*HLDA + cc) >> 1] = lp;
            }
        }
        __syncthreads();

        // ---- GEMM2 partial: acc2 += h_chunk(64x128) @ W2[chunk, :] ----
        #pragma unroll
        for (int s = 0; s < 8; ++s) {
            const int k0  = s*16;
            const int row = wm2*16 + r;
            int base = row*HLDA + k0 + c2;
            uint32_t ah[4], al[4];
            ah[0] = hhi32[base >> 1];
            ah[1] = hhi32[(base + 8*HLDA) >> 1];
            ah[2] = hhi32[(base + 8) >> 1];
            ah[3] = hhi32[(base + 8*HLDA + 8) >> 1];
            al[0] = hlo32[base >> 1];
            al[1] = hlo32[(base + 8*HLDA) >> 1];
            al[2] = hlo32[(base + 8) >> 1];
            al[3] = hlo32[(base + 8*HLDA + 8) >> 1];
            const int S = ch*8 + s;
            #pragma unroll
            for (int nt = 0; nt < 6; ++nt) {
                int n = wn2*48 + nt*8 + nlane;
                const uint32_t* bph = g_W2hi + ((size_t)S*96 + n)*8;
                const uint32_t* bpl = g_W2lo + ((size_t)S*96 + n)*8;
                uint32_t bh0 = bph[q], bh1 = bph[4+q];
                uint32_t bl0 = bpl[q], bl1 = bpl[4+q];
                mma16816(acc2[nt], ah, bh0, bh1);
                mma16816(acc2[nt], ah, bl0, bl1);
                mma16816(acc2[nt], al, bh0, bh1);
            }
        }
    }

    // ---- epilogue: bias + residual, in place ----
    {
        const int m0 = wm2*16;
        #pragma unroll
        for (int nt = 0; nt < 6; ++nt) {
            int cg = wn2*48 + nt*8 + c2;
            float2 bia = *(const float2*)(fc2_b + cg);
            size_t b0 = (size_t)(tok0 + m0 + r)*96 + cg;
            float2 sk0 = *(const float2*)(xio + b0);
            float2 o0;
            o0.x = acc2[nt][0] + bia.x + sk0.x;
            o0.y = acc2[nt][1] + bia.y + sk0.y;
            *(float2*)(xio + b0) = o0;
            size_t b1 = b0 + (size_t)8*96;
            float2 sk1 = *(const float2*)(xio + b1);
            float2 o1;
            o1.x = acc2[nt][2] + bia.x + sk1.x;
            o1.y = acc2[nt][3] + bia.y + sk1.y;
            *(float2*)(xio + b1) = o1;
        }
    }
}

// ---------------------------------------------------------------------------
extern "C" void kernel_launch(void* const* d_in, const int* in_sizes, int n_in,
                              void* d_out, int out_size)
{
    const float* x      = (const float*)d_in[0];
    const float* g1     = (const float*)d_in[1];
    const float* b1     = (const float*)d_in[2];
    const float* qkv_w  = (const float*)d_in[3];
    const float* qkv_b  = (const float*)d_in[4];
    const float* proj_w = (const float*)d_in[5];
    const float* proj_b = (const float*)d_in[6];
    const float* rpb    = (const float*)d_in[7];
    const float* g2     = (const float*)d_in[8];
    const float* b2     = (const float*)d_in[9];
    const float* fc1_w  = (const float*)d_in[10];
    const float* fc1_b  = (const float*)d_in[11];
    const float* fc2_w  = (const float*)d_in[12];
    const float* fc2_b  = (const float*)d_in[13];
    const int*   relidx = (const int*)d_in[14];
    const float* amask  = (const float*)d_in[15];
    float* out = (float*)d_out;

    const int smem1 = (4*96*MPAD + 3*NTOK*SPAD)*(int)sizeof(float) + NTOK*(int)sizeof(int);
    const int smem2 = (2*64*XLDA + 2*64*HLDA)*(int)sizeof(__nv_bfloat16);
    cudaFuncSetAttribute(swin_attn_kernel, cudaFuncAttributeMaxDynamicSharedMemorySize, smem1);
    cudaFuncSetAttribute(swin_mlp_mma,     cudaFuncAttributeMaxDynamicSharedMemorySize, smem2);

    pack_mlp_weights<<<72, 256>>>(fc1_w, fc2_w);
    swin_attn_kernel<<<NWIN_TOT, 288, smem1>>>(x, g1, b1, qkv_w, qkv_b, proj_w, proj_b,
                                               rpb, relidx, amask, out);
    swin_mlp_mma<<<NBLK2, 256, smem2>>>(g2, b2, fc1_b, fc2_b, out);
}

// round 3
// speedup vs baseline: 3.3155x; 2.1696x over previous
#include <cuda_runtime.h>
#include <cuda_bf16.h>
#include <math.h>
#include <stdint.h>

// Problem constants
#define HH      112
#define WW2     112
#define CC      96
#define SHIFT_  3
#define NTOK    49
#define QKSCALE 0.17677669529663687f
#define NWIN_TOT 16384
#define NBLK2    12544     // 802816 / 64

// ===========================================================================
// bf16 MMA helpers
// ===========================================================================
__device__ __forceinline__ void mma16816(float d[4], const uint32_t a[4],
                                         uint32_t b0, uint32_t b1) {
    asm volatile(
        "mma.sync.aligned.m16n8k16.row.col.f32.bf16.bf16.f32 "
        "{%0,%1,%2,%3},{%4,%5,%6,%7},{%8,%9},{%0,%1,%2,%3};"
        : "+f"(d[0]), "+f"(d[1]), "+f"(d[2]), "+f"(d[3])
        : "r"(a[0]), "r"(a[1]), "r"(a[2]), "r"(a[3]), "r"(b0), "r"(b1));
}

__device__ __forceinline__ uint32_t packbf(float x0, float x1) {
    uint32_t p;
    asm("cvt.rn.bf16x2.f32 %0, %1, %2;" : "=r"(p) : "f"(x1), "f"(x0));
    return p;
}

__device__ __forceinline__ void split2(float x0, float x1,
                                       uint32_t& hi, uint32_t& lo) {
    uint32_t hp = packbf(x0, x1);
    __nv_bfloat162 hb = *reinterpret_cast<__nv_bfloat162*>(&hp);
    float l0 = x0 - __bfloat162float(hb.x);
    float l1 = x1 - __bfloat162float(hb.y);
    hi = hp; lo = packbf(l0, l1);
}

__device__ __forceinline__ float gelu_exact(float v) {
    return 0.5f * v * (1.0f + erff(v * 0.7071067811865476f));
}

// Pre-packed weights in B-fragment order: [k16step][n][pair 0..7] bf16x2
__device__ uint32_t g_W1hi[6 * 384 * 8];
__device__ uint32_t g_W1lo[6 * 384 * 8];
__device__ uint32_t g_W2hi[24 * 96 * 8];
__device__ uint32_t g_W2lo[24 * 96 * 8];
__device__ uint32_t g_Wqh [6 * 288 * 8];
__device__ uint32_t g_Wql [6 * 288 * 8];
__device__ uint32_t g_Wph [6 * 96 * 8];
__device__ uint32_t g_Wpl [6 * 96 * 8];
// fused rel-pos-bias + shift mask, padded to 64x64 with -1e4: [rem][h][i][j]
__device__ float g_bm[256 * 3 * 64 * 64];

__global__ void pack_weights(const float* __restrict__ fc1_w,
                             const float* __restrict__ fc2_w,
                             const float* __restrict__ qkv_w,
                             const float* __restrict__ proj_w) {
    int idx = blockIdx.x * 256 + threadIdx.x;
    if (idx >= 6 * 384 * 8) return;
    {   // fc1: 96 x 384
        int p = idx & 7, n = (idx >> 3) % 384, s = idx / (384 * 8);
        int k = s * 16 + 2 * p;
        uint32_t hi, lo;
        split2(fc1_w[k * 384 + n], fc1_w[(k + 1) * 384 + n], hi, lo);
        g_W1hi[idx] = hi; g_W1lo[idx] = lo;
    }
    if (idx < 24 * 96 * 8) {   // fc2: 384 x 96
        int p = idx & 7, n = (idx >> 3) % 96, s = idx / (96 * 8);
        int k = s * 16 + 2 * p;
        uint32_t hi, lo;
        split2(fc2_w[k * 96 + n], fc2_w[(k + 1) * 96 + n], hi, lo);
        g_W2hi[idx] = hi; g_W2lo[idx] = lo;
    }
    if (idx < 6 * 288 * 8) {   // qkv: 96 x 288 (q part pre-scaled)
        int p = idx & 7, n = (idx >> 3) % 288, s = idx / (288 * 8);
        int k = s * 16 + 2 * p;
        float sc = (n < 96) ? QKSCALE : 1.0f;
        uint32_t hi, lo;
        split2(qkv_w[k * 288 + n] * sc, qkv_w[(k + 1) * 288 + n] * sc, hi, lo);
        g_Wqh[idx] = hi; g_Wql[idx] = lo;
    }
    if (idx < 6 * 96 * 8) {    // proj: 96 x 96
        int p = idx & 7, n = (idx >> 3) % 96, s = idx / (96 * 8);
        int k = s * 16 + 2 * p;
        uint32_t hi, lo;
        split2(proj_w[k * 96 + n], proj_w[(k + 1) * 96 + n], hi, lo);
        g_Wph[idx] = hi; g_Wpl[idx] = lo;
    }
}

__global__ void build_bias_mask(const float* __restrict__ rpb,
                                const int* __restrict__ relidx,
                                const float* __restrict__ amask) {
    int idx = blockIdx.x * 256 + threadIdx.x;   // < 256*3*4096
    int j = idx & 63, i = (idx >> 6) & 63;
    int h = (idx >> 12) % 3;
    int rem = idx / 12288;
    float v = -10000.0f;
    if (i < NTOK && j < NTOK)
        v = rpb[relidx[i * NTOK + j] * 3 + h] + amask[(size_t)rem * 2401 + i * NTOK + j];
    g_bm[idx] = v;
}

// ---------------------------------------------------------------------------
// Kernel 1 (v3): LN1 + shifted-window MHSA + proj + residual, tensor cores.
// One block per window (49 tokens -> 64), 256 threads (8 warps).
// smem (bytes):
//   [0, 27648)       xlnHi[64][104] + xlnLo[64][104]   -> later probsLo[3][64][72]
//   [27648, 40960)   qHi[64][104]                      -> later aoHi[64][104]
//   [40960, 54272)   kHi[64][104]                      -> later aoLo[64][104]
//   [54272, 81920)   vHi[96][72] + vLo[96][72]
//   [81920, 109568)  probsHi[3][64][72]
//   [109568, 109824) srcI[49]
// ---------------------------------------------------------------------------
__global__ __launch_bounds__(256, 2)
void swin_attn_mma(const float* __restrict__ x,
                   const float* __restrict__ g1, const float* __restrict__ b1,
                   const float* __restrict__ qkv_b,
                   const float* __restrict__ proj_b,
                   float* __restrict__ out)
{
    extern __shared__ char sm[];
    __nv_bfloat16* xlnHi = (__nv_bfloat16*)(sm);
    __nv_bfloat16* xlnLo = (__nv_bfloat16*)(sm + 13312);
    uint32_t* xh32 = (uint32_t*)xlnHi;
    uint32_t* xl32 = (uint32_t*)xlnLo;
    uint32_t* qh32 = (uint32_t*)(sm + 27648);
    uint32_t* kh32 = (uint32_t*)(sm + 40960);
    __nv_bfloat16* vHi = (__nv_bfloat16*)(sm + 54272);
    __nv_bfloat16* vLo = (__nv_bfloat16*)(sm + 68096);
    uint32_t* vh32 = (uint32_t*)vHi;
    uint32_t* vl32 = (uint32_t*)vLo;
    uint32_t* ph32 = (uint32_t*)(sm + 81920);
    uint32_t* pl32 = (uint32_t*)(sm);          // alias xln
    uint32_t* aoh32 = qh32;                     // alias q
    uint32_t* aol32 = kh32;                     // alias k
    int* srcI = (int*)(sm + 109568);

    const int tid  = threadIdx.x;
    const int warp = tid >> 5, lane = tid & 31;
    const int r    = lane >> 2;        // fragment row / B n-lane
    const int qd   = lane & 3;         // pair selector
    const int c2   = qd * 2;
    const int w    = blockIdx.x;
    const int bimg = w >> 8;
    const int rem  = w & 255;
    const int wh   = rem >> 4, wwc = rem & 15;

    // ---- Phase 0: LN + shifted gather -> xln hi/lo bf16 ----
    {
        float ga = g1[lane], gb = g1[lane+32], gc = g1[lane+64];
        float ba = b1[lane], bb = b1[lane+32], bc = b1[lane+64];
        for (int t = warp; t < NTOK; t += 8) {
            int ii = t / 7, jj = t - ii*7;
            int oh = wh*7 + ii + SHIFT_; if (oh >= HH)  oh -= HH;
            int ow = wwc*7 + jj + SHIFT_; if (ow >= WW2) ow -= WW2;
            int src = (bimg*HH + oh)*WW2 + ow;
            if (lane == 0) srcI[t] = src;
            const float* xr = x + (size_t)src*CC;
            float v0 = xr[lane], v1 = xr[lane+32], v2 = xr[lane+64];
            float s = v0 + v1 + v2;
            #pragma unroll
            for (int o = 16; o; o >>= 1) s += __shfl_xor_sync(0xffffffffu, s, o);
            float mean = s * (1.0f/96.0f);
            float d0 = v0-mean, d1 = v1-mean, d2 = v2-mean;
            float q2 = d0*d0 + d1*d1 + d2*d2;
            #pragma unroll
            for (int o = 16; o; o >>= 1) q2 += __shfl_xor_sync(0xffffffffu, q2, o);
            float rstd = rsqrtf(q2*(1.0f/96.0f) + 1e-5f);
            float y0 = d0*rstd*ga + ba, y1 = d1*rstd*gb + bb, y2 = d2*rstd*gc + bc;
            __nv_bfloat16 h0 = __float2bfloat16_rn(y0);
            __nv_bfloat16 h1 = __float2bfloat16_rn(y1);
            __nv_bfloat16 h2 = __float2bfloat16_rn(y2);
            xlnHi[t*104 + lane]    = h0;
            xlnHi[t*104 + lane+32] = h1;
            xlnHi[t*104 + lane+64] = h2;
            xlnLo[t*104 + lane]    = __float2bfloat16_rn(y0 - __bfloat162float(h0));
            xlnLo[t*104 + lane+32] = __float2bfloat16_rn(y1 - __bfloat162float(h1));
            xlnLo[t*104 + lane+64] = __float2bfloat16_rn(y2 - __bfloat162float(h2));
        }
        __nv_bfloat16 z = __float2bfloat16_rn(0.0f);
        for (int idx = tid; idx < 15*96; idx += 256) {
            int rr = NTOK + idx/96, cc = idx - (idx/96)*96;
            xlnHi[rr*104 + cc] = z;
            xlnLo[rr*104 + cc] = z;
        }
    }
    __syncthreads();

    // ---- Phase 1: QKV GEMM (M=64, K=96, N=288), split 3-MMA ----
    {
        const int wm = warp >> 2, wn = warp & 3;
        for (int g = 0; g < 3; ++g) {
            float acc[3][2][4];
            #pragma unroll
            for (int a = 0; a < 3; ++a)
                #pragma unroll
                for (int b = 0; b < 2; ++b)
                    #pragma unroll
                    for (int c = 0; c < 4; ++c) acc[a][b][c] = 0.f;
            #pragma unroll
            for (int s = 0; s < 6; ++s) {
                uint32_t ah[2][4], al[2][4];
                #pragma unroll
                for (int mt = 0; mt < 2; ++mt) {
                    int w0 = (wm*32 + mt*16 + r)*52 + s*8 + qd;
                    ah[mt][0] = xh32[w0];       ah[mt][1] = xh32[w0 + 8*52];
                    ah[mt][2] = xh32[w0 + 4];   ah[mt][3] = xh32[w0 + 8*52 + 4];
                    al[mt][0] = xl32[w0];       al[mt][1] = xl32[w0 + 8*52];
                    al[mt][2] = xl32[w0 + 4];   al[mt][3] = xl32[w0 + 8*52 + 4];
                }
                #pragma unroll
                for (int nt = 0; nt < 3; ++nt) {
                    int n = wn*72 + g*24 + nt*8 + r;
                    const uint32_t* bh = g_Wqh + ((size_t)s*288 + n)*8;
                    const uint32_t* bl = g_Wql + ((size_t)s*288 + n)*8;
                    uint32_t bh0 = bh[qd], bh1 = bh[4+qd];
                    uint32_t bl0 = bl[qd], bl1 = bl[4+qd];
                    #pragma unroll
                    for (int mt = 0; mt < 2; ++mt) {
                        mma16816(acc[nt][mt], ah[mt], bh0, bh1);
                        mma16816(acc[nt][mt], ah[mt], bl0, bl1);
                        mma16816(acc[nt][mt], al[mt], bh0, bh1);
                    }
                }
            }
            // epilogue: +bias, route to qHi / kHi / vT hi+lo
            #pragma unroll
            for (int nt = 0; nt < 3; ++nt) {
                int nb = wn*72 + g*24 + nt*8 + c2;
                float b0v = qkv_b[nb], b1v = qkv_b[nb+1];
                if (nb < 96) { b0v *= QKSCALE; b1v *= QKSCALE; }
                #pragma unroll
                for (int mt = 0; mt < 2; ++mt) {
                    int row = wm*32 + mt*16 + r;
                    float v00 = acc[nt][mt][0] + b0v, v01 = acc[nt][mt][1] + b1v;
                    float v10 = acc[nt][mt][2] + b0v, v11 = acc[nt][mt][3] + b1v;
                    if (nb < 96) {
                        qh32[(row*104 + nb) >> 1]     = packbf(v00, v01);
                        qh32[((row+8)*104 + nb) >> 1] = packbf(v10, v11);
                    } else if (nb < 192) {
                        int c = nb - 96;
                        kh32[(row*104 + c) >> 1]      = packbf(v00, v01);
                        kh32[((row+8)*104 + c) >> 1]  = packbf(v10, v11);
                    } else {
                        int c = nb - 192;
                        __nv_bfloat16 h;
                        h = __float2bfloat16_rn(v00);
                        vHi[c*72 + row] = h;
                        vLo[c*72 + row] = __float2bfloat16_rn(v00 - __bfloat162float(h));
                        h = __float2bfloat16_rn(v01);
                        vHi[(c+1)*72 + row] = h;
                        vLo[(c+1)*72 + row] = __float2bfloat16_rn(v01 - __bfloat162float(h));
                        h = __float2bfloat16_rn(v10);
                        vHi[c*72 + row + 8] = h;
                        vLo[c*72 + row + 8] = __float2bfloat16_rn(v10 - __bfloat162float(h));
                        h = __float2bfloat16_rn(v11);
                        vHi[(c+1)*72 + row + 8] = h;
                        vLo[(c+1)*72 + row + 8] = __float2bfloat16_rn(v11 - __bfloat162float(h));
                    }
                }
            }
        }
    }
    __syncthreads();

    // ---- Phase 2: scores (QK^T, bf16) + fused bias/mask + in-reg softmax ----
    for (int u = warp; u < 12; u += 8) {
        int h = u >> 2, mt = u & 3;
        int rowb = mt * 16;
        float acc[8][4];
        #pragma unroll
        for (int a = 0; a < 8; ++a)
            #pragma unroll
            for (int c = 0; c < 4; ++c) acc[a][c] = 0.f;
        #pragma unroll
        for (int s = 0; s < 2; ++s) {
            uint32_t a[4];
            int w0 = (rowb + r)*52 + h*16 + s*8 + qd;
            a[0] = qh32[w0];     a[1] = qh32[w0 + 8*52];
            a[2] = qh32[w0 + 4]; a[3] = qh32[w0 + 8*52 + 4];
            #pragma unroll
            for (int nt = 0; nt < 8; ++nt) {
                int wb = (nt*8 + r)*52 + h*16 + s*8 + qd;
                mma16816(acc[nt], a, kh32[wb], kh32[wb + 4]);
            }
        }
        // fused bias+mask, softmax across row (4 lanes per row)
        const float* bmb = g_bm + ((size_t)(rem*3 + h)) * 4096;
        int i0 = rowb + r, i1 = i0 + 8;
        float m0 = -1e30f, m1 = -1e30f;
        #pragma unroll
        for (int nt = 0; nt < 8; ++nt) {
            int j = nt*8 + c2;
            float2 bm0 = *(const float2*)(bmb + i0*64 + j);
            float2 bm1 = *(const float2*)(bmb + i1*64 + j);
            acc[nt][0] += bm0.x; acc[nt][1] += bm0.y;
            acc[nt][2] += bm1.x; acc[nt][3] += bm1.y;
            m0 = fmaxf(m0, fmaxf(acc[nt][0], acc[nt][1]));
            m1 = fmaxf(m1, fmaxf(acc[nt][2], acc[nt][3]));
        }
        m0 = fmaxf(m0, __shfl_xor_sync(0xffffffffu, m0, 1));
        m0 = fmaxf(m0, __shfl_xor_sync(0xffffffffu, m0, 2));
        m1 = fmaxf(m1, __shfl_xor_sync(0xffffffffu, m1, 1));
        m1 = fmaxf(m1, __shfl_xor_sync(0xffffffffu, m1, 2));
        float s0 = 0.f, s1 = 0.f;
        #pragma unroll
        for (int nt = 0; nt < 8; ++nt) {
            acc[nt][0] = __expf(acc[nt][0] - m0);
            acc[nt][1] = __expf(acc[nt][1] - m0);
            acc[nt][2] = __expf(acc[nt][2] - m1);
            acc[nt][3] = __expf(acc[nt][3] - m1);
            s0 += acc[nt][0] + acc[nt][1];
            s1 += acc[nt][2] + acc[nt][3];
        }
        s0 += __shfl_xor_sync(0xffffffffu, s0, 1);
        s0 += __shfl_xor_sync(0xffffffffu, s0, 2);
        s1 += __shfl_xor_sync(0xffffffffu, s1, 1);
        s1 += __shfl_xor_sync(0xffffffffu, s1, 2);
        float inv0 = 1.0f / s0, inv1 = 1.0f / s1;
        #pragma unroll
        for (int nt = 0; nt < 8; ++nt) {
            uint32_t hp, lp;
            split2(acc[nt][0]*inv0, acc[nt][1]*inv0, hp, lp);
            int w0 = (h*64 + i0)*36 + nt*4 + qd;
            ph32[w0] = hp; pl32[w0] = lp;
            split2(acc[nt][2]*inv1, acc[nt][3]*inv1, hp, lp);
            int w1 = (h*64 + i1)*36 + nt*4 + qd;
            ph32[w1] = hp; pl32[w1] = lp;
        }
    }
    __syncthreads();

    // ---- Phase 3: A.V (split 3-MMA) -> attn_out hi/lo (alias q/k) ----
    {
        const int wm2 = warp >> 1, wn2 = warp & 1;
        float acc[6][4];
        #pragma unroll
        for (int a = 0; a < 6; ++a)
            #pragma unroll
            for (int c = 0; c < 4; ++c) acc[a][c] = 0.f;
        const int hA = wn2, hB = wn2 + 1;    // heads covered by this n-half
        #pragma unroll
        for (int ks = 0; ks < 4; ++ks) {
            uint32_t pAh[4], pAl[4], pBh[4], pBl[4];
            int row = wm2*16 + r;
            int wA = (hA*64 + row)*36 + ks*8 + qd;
            pAh[0] = ph32[wA];     pAh[1] = ph32[wA + 8*36];
            pAh[2] = ph32[wA + 4]; pAh[3] = ph32[wA + 8*36 + 4];
            pAl[0] = pl32[wA];     pAl[1] = pl32[wA + 8*36];
            pAl[2] = pl32[wA + 4]; pAl[3] = pl32[wA + 8*36 + 4];
            int wB = (hB*64 + row)*36 + ks*8 + qd;
            pBh[0] = ph32[wB];     pBh[1] = ph32[wB + 8*36];
            pBh[2] = ph32[wB + 4]; pBh[3] = ph32[wB + 8*36 + 4];
            pBl[0] = pl32[wB];     pBl[1] = pl32[wB + 8*36];
            pBl[2] = pl32[wB + 4]; pBl[3] = pl32[wB + 8*36 + 4];
            #pragma unroll
            for (int nt = 0; nt < 6; ++nt) {
                int c0 = wn2*48 + nt*8;
                int wb = (c0 + r)*36 + ks*8 + qd;
                uint32_t bh0 = vh32[wb], bh1 = vh32[wb + 4];
                uint32_t bl0 = vl32[wb], bl1 = vl32[wb + 4];
                const uint32_t* ph = ((c0 >> 5) == hA) ? pAh : pBh;
                const uint32_t* pl = ((c0 >> 5) == hA) ? pAl : pBl;
                mma16816(acc[nt], ph, bh0, bh1);
                mma16816(acc[nt], ph, bl0, bl1);
                mma16816(acc[nt], pl, bh0, bh1);
            }
        }
        __syncthreads();   // q/k reads (phase 2 done) before ao overwrite
        #pragma unroll
        for (int nt = 0; nt < 6; ++nt) {
            int c = wn2*48 + nt*8 + c2;
            int i0 = wm2*16 + r;
            uint32_t hp, lp;
            split2(acc[nt][0], acc[nt][1], hp, lp);
            aoh32[(i0*104 + c) >> 1] = hp;
            aol32[(i0*104 + c) >> 1] = lp;
            split2(acc[nt][2], acc[nt][3], hp, lp);
            aoh32[((i0+8)*104 + c) >> 1] = hp;
            aol32[((i0+8)*104 + c) >> 1] = lp;
        }
    }
    __syncthreads();

    // ---- Phase 4: proj (split 3-MMA) + bias + residual -> gmem ----
    {
        const int wm = warp >> 2, wn = warp & 3;
        float acc[3][2][4];
        #pragma unroll
        for (int a = 0; a < 3; ++a)
            #pragma unroll
            for (int b = 0; b < 2; ++b)
                #pragma unroll
                for (int c = 0; c < 4; ++c) acc[a][b][c] = 0.f;
        #pragma unroll
        for (int s = 0; s < 6; ++s) {
            uint32_t ah[2][4], al[2][4];
            #pragma unroll
            for (int mt = 0; mt < 2; ++mt) {
                int w0 = (wm*32 + mt*16 + r)*52 + s*8 + qd;
                ah[mt][0] = aoh32[w0];     ah[mt][1] = aoh32[w0 + 8*52];
                ah[mt][2] = aoh32[w0 + 4]; ah[mt][3] = aoh32[w0 + 8*52 + 4];
                al[mt][0] = aol32[w0];     al[mt][1] = aol32[w0 + 8*52];
                al[mt][2] = aol32[w0 + 4]; al[mt][3] = aol32[w0 + 8*52 + 4];
            }
            #pragma unroll
            for (int nt = 0; nt < 3; ++nt) {
                int n = wn*24 + nt*8 + r;
                const uint32_t* bh = g_Wph + ((size_t)s*96 + n)*8;
                const uint32_t* bl = g_Wpl + ((size_t)s*96 + n)*8;
                uint32_t bh0 = bh[qd], bh1 = bh[4+qd];
                uint32_t bl0 = bl[qd], bl1 = bl[4+qd];
                #pragma unroll
                for (int mt = 0; mt < 2; ++mt) {
                    mma16816(acc[nt][mt], ah[mt], bh0, bh1);
                    mma16816(acc[nt][mt], ah[mt], bl0, bl1);
                    mma16816(acc[nt][mt], al[mt], bh0, bh1);
                }
            }
        }
        #pragma unroll
        for (int nt = 0; nt < 3; ++nt) {
            int c = wn*24 + nt*8 + c2;
            float2 pb = *(const float2*)(proj_b + c);
            #pragma unroll
            for (int mt = 0; mt < 2; ++mt) {
                int i0 = wm*32 + mt*16 + r;
                if (i0 < NTOK) {
                    size_t base = (size_t)srcI[i0]*96 + c;
                    float2 xr = *(const float2*)(x + base);
                    float2 o;
                    o.x = acc[nt][mt][0] + pb.x + xr.x;
                    o.y = acc[nt][mt][1] + pb.y + xr.y;
                    *(float2*)(out + base) = o;
                }
                int i1 = i0 + 8;
                if (i1 < NTOK) {
                    size_t base = (size_t)srcI[i1]*96 + c;
                    float2 xr = *(const float2*)(x + base);
                    float2 o;
                    o.x = acc[nt][mt][2] + pb.x + xr.x;
                    o.y = acc[nt][mt][3] + pb.y + xr.y;
                    *(float2*)(out + base) = o;
                }
            }
        }
    }
}

// ---------------------------------------------------------------------------
// Kernel 2: LN2 + MLP via bf16 split tensor-core MMA (unchanged from R2)
// ---------------------------------------------------------------------------
#define XLDA 104
#define HLDA 136

__global__ __launch_bounds__(256, 2)
void swin_mlp_mma(const float* __restrict__ g2, const float* __restrict__ b2,
                  const float* __restrict__ fc1_b, const float* __restrict__ fc2_b,
                  float* __restrict__ xio)
{
    extern __shared__ char smem_raw[];
    __nv_bfloat16* xhi = (__nv_bfloat16*)smem_raw;
    __nv_bfloat16* xlo = xhi + 64*XLDA;
    __nv_bfloat16* hhi = xlo + 64*XLDA;
    __nv_bfloat16* hlo = hhi + 64*HLDA;
    uint32_t* xhi32 = (uint32_t*)xhi;
    uint32_t* xlo32 = (uint32_t*)xlo;
    uint32_t* hhi32 = (uint32_t*)hhi;
    uint32_t* hlo32 = (uint32_t*)hlo;

    const int tid   = threadIdx.x;
    const int warp  = tid >> 5, lane = tid & 31;
    const int tok0  = blockIdx.x * 64;
    const int r     = lane >> 2;
    const int c2    = (lane & 3) * 2;
    const int q     = lane & 3;
    const int nlane = lane >> 2;

    {
        float ga = g2[lane], gb = g2[lane+32], gc = g2[lane+64];
        float ba = b2[lane], bb = b2[lane+32], bc = b2[lane+64];
        for (int t = warp; t < 64; t += 8) {
            const float* xr = xio + (size_t)(tok0+t)*96;
            float v0 = xr[lane], v1 = xr[lane+32], v2 = xr[lane+64];
            float s = v0 + v1 + v2;
            #pragma unroll
            for (int o = 16; o; o >>= 1) s += __shfl_xor_sync(0xffffffffu, s, o);
            float mean = s * (1.0f/96.0f);
            float d0 = v0-mean, d1 = v1-mean, d2 = v2-mean;
            float q2 = d0*d0 + d1*d1 + d2*d2;
            #pragma unroll
            for (int o = 16; o; o >>= 1) q2 += __shfl_xor_sync(0xffffffffu, q2, o);
            float rstd = rsqrtf(q2*(1.0f/96.0f) + 1e-5f);
            float y0 = d0*rstd*ga + ba;
            float y1 = d1*rstd*gb + bb;
            float y2 = d2*rstd*gc + bc;
            __nv_bfloat16 h0 = __float2bfloat16_rn(y0);
            __nv_bfloat16 h1 = __float2bfloat16_rn(y1);
            __nv_bfloat16 h2 = __float2bfloat16_rn(y2);
            xhi[t*XLDA + lane]      = h0;
            xhi[t*XLDA + lane + 32] = h1;
            xhi[t*XLDA + lane + 64] = h2;
            xlo[t*XLDA + lane]      = __float2bfloat16_rn(y0 - __bfloat162float(h0));
            xlo[t*XLDA + lane + 32] = __float2bfloat16_rn(y1 - __bfloat162float(h1));
            xlo[t*XLDA + lane + 64] = __float2bfloat16_rn(y2 - __bfloat162float(h2));
        }
    }
    __syncthreads();

    float acc2[6][4];
    #pragma unroll
    for (int i = 0; i < 6; ++i)
        #pragma unroll
        for (int j = 0; j < 4; ++j) acc2[i][j] = 0.f;

    const int wm1 = warp >> 2, wn1 = warp & 3;
    const int wm2 = warp >> 1, wn2 = warp & 1;

    for (int ch = 0; ch < 3; ++ch) {
        float acc1[2][4][4];
        #pragma unroll
        for (int a = 0; a < 2; ++a)
            #pragma unroll
            for (int b = 0; b < 4; ++b)
                #pragma unroll
                for (int c = 0; c < 4; ++c) acc1[a][b][c] = 0.f;

        #pragma unroll
        for (int s = 0; s < 6; ++s) {
            const int k0 = s*16;
            uint32_t ah[2][4], al[2][4];
            #pragma unroll
            for (int mt = 0; mt < 2; ++mt) {
                int row  = wm1*32 + mt*16 + r;
                int base = row*XLDA + k0 + c2;
                ah[mt][0] = xhi32[base >> 1];
                ah[mt][1] = xhi32[(base + 8*XLDA) >> 1];
                ah[mt][2] = xhi32[(base + 8) >> 1];
                ah[mt][3] = xhi32[(base + 8*XLDA + 8) >> 1];
                al[mt][0] = xlo32[base >> 1];
                al[mt][1] = xlo32[(base + 8*XLDA) >> 1];
                al[mt][2] = xlo32[(base + 8) >> 1];
                al[mt][3] = xlo32[(base + 8*XLDA + 8) >> 1];
            }
            #pragma unroll
            for (int nt = 0; nt < 4; ++nt) {
                int n = ch*128 + wn1*32 + nt*8 + nlane;
                const uint32_t* bph = g_W1hi + ((size_t)s*384 + n)*8;
                const uint32_t* bpl = g_W1lo + ((size_t)s*384 + n)*8;
                uint32_t bh0 = bph[q],   bh1 = bph[4+q];
                uint32_t bl0 = bpl[q],   bl1 = bpl[4+q];
                #pragma unroll
                for (int mt = 0; mt < 2; ++mt) {
                    mma16816(acc1[mt][nt], ah[mt], bh0, bh1);
                    mma16816(acc1[mt][nt], ah[mt], bl0, bl1);
                    mma16816(acc1[mt][nt], al[mt], bh0, bh1);
                }
            }
        }

        __syncthreads();

        #pragma unroll
        for (int mt = 0; mt < 2; ++mt) {
            int row0 = wm1*32 + mt*16 + r;
            #pragma unroll
            for (int nt = 0; nt < 4; ++nt) {
                int cc = wn1*32 + nt*8 + c2;
                float2 bia = *(const float2*)(fc1_b + ch*128 + cc);
                float g00 = gelu_exact(acc1[mt][nt][0] + bia.x);
                float g01 = gelu_exact(acc1[mt][nt][1] + bia.y);
                uint32_t hp, lp;
                split2(g00, g01, hp, lp);
                hhi32[(row0*HLDA + cc) >> 1] = hp;
                hlo32[(row0*HLDA + cc) >> 1] = lp;
                float g10 = gelu_exact(acc1[mt][nt][2] + bia.x);
                float g11 = gelu_exact(acc1[mt][nt][3] + bia.y);
                split2(g10, g11, hp, lp);
                hhi32[((row0+8)*HLDA + cc) >> 1] = hp;
                hlo32[((row0+8)*HLDA + cc) >> 1] = lp;
            }
        }
        __syncthreads();

        #pragma unroll
        for (int s = 0; s < 8; ++s) {
            const int k0  = s*16;
            const int row = wm2*16 + r;
            int base = row*HLDA + k0 + c2;
            uint32_t ah[4], al[4];
            ah[0] = hhi32[base >> 1];
            ah[1] = hhi32[(base + 8*HLDA) >> 1];
            ah[2] = hhi32[(base + 8) >> 1];
            ah[3] = hhi32[(base + 8*HLDA + 8) >> 1];
            al[0] = hlo32[base >> 1];
            al[1] = hlo32[(base + 8*HLDA) >> 1];
            al[2] = hlo32[(base + 8) >> 1];
            al[3] = hlo32[(base + 8*HLDA + 8) >> 1];
            const int S = ch*8 + s;
            #pragma unroll
            for (int nt = 0; nt < 6; ++nt) {
                int n = wn2*48 + nt*8 + nlane;
                const uint32_t* bph = g_W2hi + ((size_t)S*96 + n)*8;
                const uint32_t* bpl = g_W2lo + ((size_t)S*96 + n)*8;
                uint32_t bh0 = bph[q], bh1 = bph[4+q];
                uint32_t bl0 = bpl[q], bl1 = bpl[4+q];
                mma16816(acc2[nt], ah, bh0, bh1);
                mma16816(acc2[nt], ah, bl0, bl1);
                mma16816(acc2[nt], al, bh0, bh1);
            }
        }
    }

    {
        const int m0 = wm2*16;
        #pragma unroll
        for (int nt = 0; nt < 6; ++nt) {
            int cg = wn2*48 + nt*8 + c2;
            float2 bia = *(const float2*)(fc2_b + cg);
            size_t b0 = (size_t)(tok0 + m0 + r)*96 + cg;
            float2 sk0 = *(const float2*)(xio + b0);
            float2 o0;
            o0.x = acc2[nt][0] + bia.x + sk0.x;
            o0.y = acc2[nt][1] + bia.y + sk0.y;
            *(float2*)(xio + b0) = o0;
            size_t b1 = b0 + (size_t)8*96;
            float2 sk1 = *(const float2*)(xio + b1);
            float2 o1;
            o1.x = acc2[nt][2] + bia.x + sk1.x;
            o1.y = acc2[nt][3] + bia.y + sk1.y;
            *(float2*)(xio + b1) = o1;
        }
    }
}

// ---------------------------------------------------------------------------
extern "C" void kernel_launch(void* const* d_in, const int* in_sizes, int n_in,
                              void* d_out, int out_size)
{
    const float* x      = (const float*)d_in[0];
    const float* g1     = (const float*)d_in[1];
    const float* b1     = (const float*)d_in[2];
    const float* qkv_w  = (const float*)d_in[3];
    const float* qkv_b  = (const float*)d_in[4];
    const float* proj_w = (const float*)d_in[5];
    const float* proj_b = (const float*)d_in[6];
    const float* rpb    = (const float*)d_in[7];
    const float* g2     = (const float*)d_in[8];
    const float* b2     = (const float*)d_in[9];
    const float* fc1_w  = (const float*)d_in[10];
    const float* fc1_b  = (const float*)d_in[11];
    const float* fc2_w  = (const float*)d_in[12];
    const float* fc2_b  = (const float*)d_in[13];
    const int*   relidx = (const int*)d_in[14];
    const float* amask  = (const float*)d_in[15];
    float* out = (float*)d_out;

    const int smem1 = 109824;
    const int smem2 = (2*64*XLDA + 2*64*HLDA)*(int)sizeof(__nv_bfloat16);
    cudaFuncSetAttribute(swin_attn_mma, cudaFuncAttributeMaxDynamicSharedMemorySize, smem1);
    cudaFuncSetAttribute(swin_mlp_mma,  cudaFuncAttributeMaxDynamicSharedMemorySize, smem2);

    pack_weights<<<72, 256>>>(fc1_w, fc2_w, qkv_w, proj_w);
    build_bias_mask<<<12288, 256>>>(rpb, relidx, amask);
    swin_attn_mma<<<NWIN_TOT, 256, smem1>>>(x, g1, b1, qkv_b, proj_b, out);
    swin_mlp_mma<<<NBLK2, 256, smem2>>>(g2, b2, fc1_b, fc2_b, out);
}

// round 4
// speedup vs baseline: 3.9381x; 1.1878x over previous
#include <cuda_runtime.h>
#include <cuda_bf16.h>
#include <math.h>
#include <stdint.h>

// Problem constants
#define HH      112
#define WW2     112
#define CC      96
#define SHIFT_  3
#define NTOK    49
#define QKSCALE 0.17677669529663687f
#define NWIN_TOT 16384
#define NBLK2    12544     // 802816 / 64

// ===========================================================================
// MMA / LDSM helpers
// ===========================================================================
__device__ __forceinline__ void mma16816(float d[4], const uint32_t a[4],
                                         uint32_t b0, uint32_t b1) {
    asm volatile(
        "mma.sync.aligned.m16n8k16.row.col.f32.bf16.bf16.f32 "
        "{%0,%1,%2,%3},{%4,%5,%6,%7},{%8,%9},{%0,%1,%2,%3};"
        : "+f"(d[0]), "+f"(d[1]), "+f"(d[2]), "+f"(d[3])
        : "r"(a[0]), "r"(a[1]), "r"(a[2]), "r"(a[3]), "r"(b0), "r"(b1));
}

__device__ __forceinline__ void ldsm4(uint32_t r[4], uint32_t saddr) {
    asm volatile("ldmatrix.sync.aligned.m8n8.x4.shared.b16 {%0,%1,%2,%3}, [%4];"
        : "=r"(r[0]), "=r"(r[1]), "=r"(r[2]), "=r"(r[3]) : "r"(saddr));
}

__device__ __forceinline__ uint32_t cvsm(const void* p) {
    return (uint32_t)__cvta_generic_to_shared(p);
}

__device__ __forceinline__ uint32_t packbf(float x0, float x1) {
    uint32_t p;
    asm("cvt.rn.bf16x2.f32 %0, %1, %2;" : "=r"(p) : "f"(x1), "f"(x0));
    return p;
}

__device__ __forceinline__ void split2(float x0, float x1,
                                       uint32_t& hi, uint32_t& lo) {
    uint32_t hp = packbf(x0, x1);
    __nv_bfloat162 hb = *reinterpret_cast<__nv_bfloat162*>(&hp);
    float l0 = x0 - __bfloat162float(hb.x);
    float l1 = x1 - __bfloat162float(hb.y);
    hi = hp; lo = packbf(l0, l1);
}

__device__ __forceinline__ float gelu_exact(float v) {
    return 0.5f * v * (1.0f + erff(v * 0.7071067811865476f));
}

// Pre-packed weights: [k16step s][n][q] -> uint4 (bh0, bh1, bl0, bl1)
__device__ uint4 g_W1p[6 * 384 * 4];
__device__ uint4 g_W2p[24 * 96 * 4];
__device__ uint4 g_Wqp[6 * 288 * 4];
__device__ uint4 g_Wpp[6 * 96 * 4];
// fused rel-pos-bias + shift mask, padded to 64x64 with -1e4: [rem][h][i][j]
__device__ float g_bm[256 * 3 * 64 * 64];

__global__ void pack_weights(const float* __restrict__ fc1_w,
                             const float* __restrict__ fc2_w,
                             const float* __restrict__ qkv_w,
                             const float* __restrict__ proj_w) {
    int idx = blockIdx.x * 256 + threadIdx.x;
    if (idx >= 9216) return;
    uint32_t h0, l0, h1, l1;
    {   // fc1: 96 x 384 -> 6*384*4 = 9216 entries
        int q = idx & 3, n = (idx >> 2) % 384, s = idx / 1536;
        int k = s * 16 + 2 * q;
        split2(fc1_w[k * 384 + n],       fc1_w[(k + 1) * 384 + n], h0, l0);
        split2(fc1_w[(k + 8) * 384 + n], fc1_w[(k + 9) * 384 + n], h1, l1);
        g_W1p[idx] = make_uint4(h0, h1, l0, l1);
    }
    {   // fc2: 384 x 96 -> 24*96*4 = 9216 entries
        int q = idx & 3, n = (idx >> 2) % 96, s = idx / 384;
        int k = s * 16 + 2 * q;
        split2(fc2_w[k * 96 + n],       fc2_w[(k + 1) * 96 + n], h0, l0);
        split2(fc2_w[(k + 8) * 96 + n], fc2_w[(k + 9) * 96 + n], h1, l1);
        g_W2p[idx] = make_uint4(h0, h1, l0, l1);
    }
    if (idx < 6912) {   // qkv: 96 x 288 (q cols pre-scaled)
        int q = idx & 3, n = (idx >> 2) % 288, s = idx / 1152;
        int k = s * 16 + 2 * q;
        float sc = (n < 96) ? QKSCALE : 1.0f;
        split2(qkv_w[k * 288 + n] * sc,       qkv_w[(k + 1) * 288 + n] * sc, h0, l0);
        split2(qkv_w[(k + 8) * 288 + n] * sc, qkv_w[(k + 9) * 288 + n] * sc, h1, l1);
        g_Wqp[idx] = make_uint4(h0, h1, l0, l1);
    }
    if (idx < 2304) {   // proj: 96 x 96
        int q = idx & 3, n = (idx >> 2) % 96, s = idx / 384;
        int k = s * 16 + 2 * q;
        split2(proj_w[k * 96 + n],       proj_w[(k + 1) * 96 + n], h0, l0);
        split2(proj_w[(k + 8) * 96 + n], proj_w[(k + 9) * 96 + n], h1, l1);
        g_Wpp[idx] = make_uint4(h0, h1, l0, l1);
    }
}

__global__ void build_bias_mask(const float* __restrict__ rpb,
                                const int* __restrict__ relidx,
                                const float* __restrict__ amask) {
    int idx = blockIdx.x * 256 + threadIdx.x;
    int j = idx & 63, i = (idx >> 6) & 63;
    int h = (idx >> 12) % 3;
    int rem = idx / 12288;
    float v = -10000.0f;
    if (i < NTOK && j < NTOK)
        v = rpb[relidx[i * NTOK + j] * 3 + h] + amask[(size_t)rem * 2401 + i * NTOK + j];
    g_bm[idx] = v;
}

// ---------------------------------------------------------------------------
// Kernel 1: LN1 + shifted-window MHSA + proj + residual, tensor cores + LDSM.
// One block per window (49 tokens -> 64), 256 threads (8 warps).
// smem bytes:
//   [0, 27648)       xlnHi[64][104] + xlnLo[64][104]   -> later probsLo
//   [27648, 40960)   qHi[64][104]                      -> later aoHi
//   [40960, 54272)   kHi[64][104]                      -> later aoLo
//   [54272, 81920)   vHi[96][72] + vLo[96][72]
//   [81920, 109568)  probsHi[3][64][72]
//   [109568, 109824) srcI[49]
// ---------------------------------------------------------------------------
__global__ __launch_bounds__(256, 2)
void swin_attn_mma(const float* __restrict__ x,
                   const float* __restrict__ g1, const float* __restrict__ b1,
                   const float* __restrict__ qkv_b,
                   const float* __restrict__ proj_b,
                   float* __restrict__ out)
{
    extern __shared__ char sm[];
    __nv_bfloat16* xlnHi = (__nv_bfloat16*)(sm);
    __nv_bfloat16* xlnLo = (__nv_bfloat16*)(sm + 13312);
    uint32_t* qh32 = (uint32_t*)(sm + 27648);
    uint32_t* kh32 = (uint32_t*)(sm + 40960);
    __nv_bfloat16* vHi = (__nv_bfloat16*)(sm + 54272);
    __nv_bfloat16* vLo = (__nv_bfloat16*)(sm + 68096);
    uint32_t* ph32 = (uint32_t*)(sm + 81920);
    uint32_t* pl32 = (uint32_t*)(sm);          // alias xln
    uint32_t* aoh32 = qh32;                     // alias q
    uint32_t* aol32 = kh32;                     // alias k
    int* srcI = (int*)(sm + 109568);

    const uint32_t smb = cvsm(sm);
    const int tid  = threadIdx.x;
    const int warp = tid >> 5, lane = tid & 31;
    const int r    = lane >> 2;
    const int qd   = lane & 3;
    const int c2   = qd * 2;
    const int la15 = lane & 15;               // A-fragment row adj
    const int kadj = (lane >> 4) << 3;        // A-fragment k adj
    const int lbn  = (lane & 7) | ((lane >> 4) << 3);   // B pair n adj
    const int kbdj = ((lane >> 3) & 1) << 3;            // B pair k adj
    const int w    = blockIdx.x;
    const int bimg = w >> 8;
    const int rem  = w & 255;
    const int wh   = rem >> 4, wwc = rem & 15;

    // ---- Phase 0: LN + shifted gather -> xln hi/lo bf16 ----
    {
        float ga = g1[lane], gb = g1[lane+32], gc = g1[lane+64];
        float ba = b1[lane], bb = b1[lane+32], bc = b1[lane+64];
        for (int t = warp; t < NTOK; t += 8) {
            int ii = t / 7, jj = t - ii*7;
            int oh = wh*7 + ii + SHIFT_; if (oh >= HH)  oh -= HH;
            int ow = wwc*7 + jj + SHIFT_; if (ow >= WW2) ow -= WW2;
            int src = (bimg*HH + oh)*WW2 + ow;
            if (lane == 0) srcI[t] = src;
            const float* xr = x + (size_t)src*CC;
            float v0 = xr[lane], v1 = xr[lane+32], v2 = xr[lane+64];
            float s = v0 + v1 + v2;
            #pragma unroll
            for (int o = 16; o; o >>= 1) s += __shfl_xor_sync(0xffffffffu, s, o);
            float mean = s * (1.0f/96.0f);
            float d0 = v0-mean, d1 = v1-mean, d2 = v2-mean;
            float q2 = d0*d0 + d1*d1 + d2*d2;
            #pragma unroll
            for (int o = 16; o; o >>= 1) q2 += __shfl_xor_sync(0xffffffffu, q2, o);
            float rstd = rsqrtf(q2*(1.0f/96.0f) + 1e-5f);
            float y0 = d0*rstd*ga + ba, y1 = d1*rstd*gb + bb, y2 = d2*rstd*gc + bc;
            __nv_bfloat16 h0 = __float2bfloat16_rn(y0);
            __nv_bfloat16 h1 = __float2bfloat16_rn(y1);
            __nv_bfloat16 h2 = __float2bfloat16_rn(y2);
            xlnHi[t*104 + lane]    = h0;
            xlnHi[t*104 + lane+32] = h1;
            xlnHi[t*104 + lane+64] = h2;
            xlnLo[t*104 + lane]    = __float2bfloat16_rn(y0 - __bfloat162float(h0));
            xlnLo[t*104 + lane+32] = __float2bfloat16_rn(y1 - __bfloat162float(h1));
            xlnLo[t*104 + lane+64] = __float2bfloat16_rn(y2 - __bfloat162float(h2));
        }
        __nv_bfloat16 z = __float2bfloat16_rn(0.0f);
        for (int idx = tid; idx < 15*96; idx += 256) {
            int rr = NTOK + idx/96, cc = idx - (idx/96)*96;
            xlnHi[rr*104 + cc] = z;
            xlnLo[rr*104 + cc] = z;
        }
    }
    __syncthreads();

    // ---- Phase 1: QKV GEMM (M=64, K=96, N=288), split 3-MMA ----
    {
        const int wm = warp >> 2, wn = warp & 3;
        const uint32_t aHi = smb + (wm*32 + la15)*208 + kadj*2;
        const uint32_t aLo = aHi + 13312;
        for (int g = 0; g < 3; ++g) {
            float acc[3][2][4];
            #pragma unroll
            for (int a = 0; a < 3; ++a)
                #pragma unroll
                for (int b = 0; b < 2; ++b)
                    #pragma unroll
                    for (int c = 0; c < 4; ++c) acc[a][b][c] = 0.f;
            #pragma unroll
            for (int s = 0; s < 6; ++s) {
                uint32_t ah[2][4], al[2][4];
                ldsm4(ah[0], aHi + s*32);
                ldsm4(ah[1], aHi + 3328 + s*32);
                ldsm4(al[0], aLo + s*32);
                ldsm4(al[1], aLo + 3328 + s*32);
                #pragma unroll
                for (int nt = 0; nt < 3; ++nt) {
                    int n = wn*72 + g*24 + nt*8 + r;
                    uint4 B = g_Wqp[(s*288 + n)*4 + qd];
                    #pragma unroll
                    for (int mt = 0; mt < 2; ++mt) {
                        mma16816(acc[nt][mt], ah[mt], B.x, B.y);
                        mma16816(acc[nt][mt], ah[mt], B.z, B.w);
                        mma16816(acc[nt][mt], al[mt], B.x, B.y);
                    }
                }
            }
            // epilogue: +bias, route to qHi / kHi / vT hi+lo
            #pragma unroll
            for (int nt = 0; nt < 3; ++nt) {
                int nb = wn*72 + g*24 + nt*8 + c2;
                float b0v = qkv_b[nb], b1v = qkv_b[nb+1];
                if (nb < 96) { b0v *= QKSCALE; b1v *= QKSCALE; }
                #pragma unroll
                for (int mt = 0; mt < 2; ++mt) {
                    int row = wm*32 + mt*16 + r;
                    float v00 = acc[nt][mt][0] + b0v, v01 = acc[nt][mt][1] + b1v;
                    float v10 = acc[nt][mt][2] + b0v, v11 = acc[nt][mt][3] + b1v;
                    if (nb < 96) {
                        qh32[(row*104 + nb) >> 1]     = packbf(v00, v01);
                        qh32[((row+8)*104 + nb) >> 1] = packbf(v10, v11);
                    } else if (nb < 192) {
                        int c = nb - 96;
                        kh32[(row*104 + c) >> 1]      = packbf(v00, v01);
                        kh32[((row+8)*104 + c) >> 1]  = packbf(v10, v11);
                    } else {
                        int c = nb - 192;
                        __nv_bfloat16 h;
                        h = __float2bfloat16_rn(v00);
                        vHi[c*72 + row] = h;
                        vLo[c*72 + row] = __float2bfloat16_rn(v00 - __bfloat162float(h));
                        h = __float2bfloat16_rn(v01);
                        vHi[(c+1)*72 + row] = h;
                        vLo[(c+1)*72 + row] = __float2bfloat16_rn(v01 - __bfloat162float(h));
                        h = __float2bfloat16_rn(v10);
                        vHi[c*72 + row + 8] = h;
                        vLo[c*72 + row + 8] = __float2bfloat16_rn(v10 - __bfloat162float(h));
                        h = __float2bfloat16_rn(v11);
                        vHi[(c+1)*72 + row + 8] = h;
                        vLo[(c+1)*72 + row + 8] = __float2bfloat16_rn(v11 - __bfloat162float(h));
                    }
                }
            }
        }
    }
    __syncthreads();

    // ---- Phase 2: scores (QK^T) + fused bias/mask + in-reg softmax ----
    for (int u = warp; u < 12; u += 8) {
        int h = u >> 2, mt = u & 3;
        int rowb = mt * 16;
        uint32_t a[4];
        ldsm4(a, smb + 27648 + (rowb + la15)*208 + (h*16 + kadj)*2);
        float acc[8][4];
        #pragma unroll
        for (int aa = 0; aa < 8; ++aa)
            #pragma unroll
            for (int c = 0; c < 4; ++c) acc[aa][c] = 0.f;
        const uint32_t kb = smb + 40960 + lbn*208 + (h*16 + kbdj)*2;
        #pragma unroll
        for (int p = 0; p < 4; ++p) {
            uint32_t b[4];
            ldsm4(b, kb + p*16*208);
            mma16816(acc[2*p],   a, b[0], b[1]);
            mma16816(acc[2*p+1], a, b[2], b[3]);
        }
        // fused bias+mask, softmax across row (4 lanes per row)
        const float* bmb = g_bm + ((size_t)(rem*3 + h)) * 4096;
        int i0 = rowb + r, i1 = i0 + 8;
        float m0 = -1e30f, m1 = -1e30f;
        #pragma unroll
        for (int nt = 0; nt < 8; ++nt) {
            int j = nt*8 + c2;
            float2 bm0 = *(const float2*)(bmb + i0*64 + j);
            float2 bm1 = *(const float2*)(bmb + i1*64 + j);
            acc[nt][0] += bm0.x; acc[nt][1] += bm0.y;
            acc[nt][2] += bm1.x; acc[nt][3] += bm1.y;
            m0 = fmaxf(m0, fmaxf(acc[nt][0], acc[nt][1]));
            m1 = fmaxf(m1, fmaxf(acc[nt][2], acc[nt][3]));
        }
        m0 = fmaxf(m0, __shfl_xor_sync(0xffffffffu, m0, 1));
        m0 = fmaxf(m0, __shfl_xor_sync(0xffffffffu, m0, 2));
        m1 = fmaxf(m1, __shfl_xor_sync(0xffffffffu, m1, 1));
        m1 = fmaxf(m1, __shfl_xor_sync(0xffffffffu, m1, 2));
        float s0 = 0.f, s1 = 0.f;
        #pragma unroll
        for (int nt = 0; nt < 8; ++nt) {
            acc[nt][0] = __expf(acc[nt][0] - m0);
            acc[nt][1] = __expf(acc[nt][1] - m0);
            acc[nt][2] = __expf(acc[nt][2] - m1);
            acc[nt][3] = __expf(acc[nt][3] - m1);
            s0 += acc[nt][0] + acc[nt][1];
            s1 += acc[nt][2] + acc[nt][3];
        }
        s0 += __shfl_xor_sync(0xffffffffu, s0, 1);
        s0 += __shfl_xor_sync(0xffffffffu, s0, 2);
        s1 += __shfl_xor_sync(0xffffffffu, s1, 1);
        s1 += __shfl_xor_sync(0xffffffffu, s1, 2);
        float inv0 = 1.0f / s0, inv1 = 1.0f / s1;
        #pragma unroll
        for (int nt = 0; nt < 8; ++nt) {
            uint32_t hp, lp;
            split2(acc[nt][0]*inv0, acc[nt][1]*inv0, hp, lp);
            int w0 = (h*64 + i0)*36 + nt*4 + qd;
            ph32[w0] = hp; pl32[w0] = lp;
            split2(acc[nt][2]*inv1, acc[nt][3]*inv1, hp, lp);
            int w1 = (h*64 + i1)*36 + nt*4 + qd;
            ph32[w1] = hp; pl32[w1] = lp;
        }
    }
    __syncthreads();

    // ---- Phase 3: A.V (split 3-MMA) -> attn_out hi/lo (alias q/k) ----
    {
        const int wm2 = warp >> 1, wn2 = warp & 1;
        const int hA = wn2, hB = wn2 + 1;
        float acc[6][4];
        #pragma unroll
        for (int a = 0; a < 6; ++a)
            #pragma unroll
            for (int c = 0; c < 4; ++c) acc[a][c] = 0.f;
        const uint32_t pAh_b = smb + 81920 + (hA*64 + wm2*16 + la15)*144 + kadj*2;
        const uint32_t pAl_b = smb +     0 + (hA*64 + wm2*16 + la15)*144 + kadj*2;
        const uint32_t pBh_b = smb + 81920 + (hB*64 + wm2*16 + la15)*144 + kadj*2;
        const uint32_t pBl_b = smb +     0 + (hB*64 + wm2*16 + la15)*144 + kadj*2;
        const uint32_t vb_h  = smb + 54272 + (wn2*48 + lbn)*144 + kbdj*2;
        const uint32_t vb_l  = vb_h + 13824;
        #pragma unroll
        for (int ks = 0; ks < 4; ++ks) {
            uint32_t pAh[4], pAl[4], pBh[4], pBl[4];
            ldsm4(pAh, pAh_b + ks*32);
            ldsm4(pAl, pAl_b + ks*32);
            ldsm4(pBh, pBh_b + ks*32);
            ldsm4(pBl, pBl_b + ks*32);
            #pragma unroll
            for (int pp = 0; pp < 3; ++pp) {
                uint32_t bh[4], bl[4];
                ldsm4(bh, vb_h + pp*2304 + ks*32);
                ldsm4(bl, vb_l + pp*2304 + ks*32);
                bool useA = (((wn2*48 + pp*16) >> 5) == hA);
                const uint32_t* ph_ = useA ? pAh : pBh;
                const uint32_t* pl_ = useA ? pAl : pBl;
                mma16816(acc[2*pp],   ph_, bh[0], bh[1]);
                mma16816(acc[2*pp],   ph_, bl[0], bl[1]);
                mma16816(acc[2*pp],   pl_, bh[0], bh[1]);
                mma16816(acc[2*pp+1], ph_, bh[2], bh[3]);
                mma16816(acc[2*pp+1], ph_, bl[2], bl[3]);
                mma16816(acc[2*pp+1], pl_, bh[2], bh[3]);
            }
        }
        #pragma unroll
        for (int nt = 0; nt < 6; ++nt) {
            int c = wn2*48 + nt*8 + c2;
            int i0 = wm2*16 + r;
            uint32_t hp, lp;
            split2(acc[nt][0], acc[nt][1], hp, lp);
            aoh32[(i0*104 + c) >> 1] = hp;
            aol32[(i0*104 + c) >> 1] = lp;
            split2(acc[nt][2], acc[nt][3], hp, lp);
            aoh32[((i0+8)*104 + c) >> 1] = hp;
            aol32[((i0+8)*104 + c) >> 1] = lp;
        }
    }
    __syncthreads();

    // ---- Phase 4: proj (split 3-MMA) + bias + residual -> gmem ----
    {
        const int wm = warp >> 2, wn = warp & 3;
        const uint32_t aHi = smb + 27648 + (wm*32 + la15)*208 + kadj*2;
        const uint32_t aLo = aHi + 13312;
        float acc[3][2][4];
        #pragma unroll
        for (int a = 0; a < 3; ++a)
            #pragma unroll
            for (int b = 0; b < 2; ++b)
                #pragma unroll
                for (int c = 0; c < 4; ++c) acc[a][b][c] = 0.f;
        #pragma unroll
        for (int s = 0; s < 6; ++s) {
            uint32_t ah[2][4], al[2][4];
            ldsm4(ah[0], aHi + s*32);
            ldsm4(ah[1], aHi + 3328 + s*32);
            ldsm4(al[0], aLo + s*32);
            ldsm4(al[1], aLo + 3328 + s*32);
            #pragma unroll
            for (int nt = 0; nt < 3; ++nt) {
                int n = wn*24 + nt*8 + r;
                uint4 B = g_Wpp[(s*96 + n)*4 + qd];
                #pragma unroll
                for (int mt = 0; mt < 2; ++mt) {
                    mma16816(acc[nt][mt], ah[mt], B.x, B.y);
                    mma16816(acc[nt][mt], ah[mt], B.z, B.w);
                    mma16816(acc[nt][mt], al[mt], B.x, B.y);
                }
            }
        }
        #pragma unroll
        for (int nt = 0; nt < 3; ++nt) {
            int c = wn*24 + nt*8 + c2;
            float2 pb = *(const float2*)(proj_b + c);
            #pragma unroll
            for (int mt = 0; mt < 2; ++mt) {
                int i0 = wm*32 + mt*16 + r;
                if (i0 < NTOK) {
                    size_t base = (size_t)srcI[i0]*96 + c;
                    float2 xr = *(const float2*)(x + base);
                    float2 o;
                    o.x = acc[nt][mt][0] + pb.x + xr.x;
                    o.y = acc[nt][mt][1] + pb.y + xr.y;
                    *(float2*)(out + base) = o;
                }
                int i1 = i0 + 8;
                if (i1 < NTOK) {
                    size_t base = (size_t)srcI[i1]*96 + c;
                    float2 xr = *(const float2*)(x + base);
                    float2 o;
                    o.x = acc[nt][mt][2] + pb.x + xr.x;
                    o.y = acc[nt][mt][3] + pb.y + xr.y;
                    *(float2*)(out + base) = o;
                }
            }
        }
    }
}

// ---------------------------------------------------------------------------
// Kernel 2: LN2 + MLP via bf16 split tensor-core MMA + LDSM.
// smem: xhi[64][104], xlo, hhi[64][136], hlo  (bases 0/13312/26624/44032)
// ---------------------------------------------------------------------------
#define XLDA 104
#define HLDA 136

__global__ __launch_bounds__(256, 2)
void swin_mlp_mma(const float* __restrict__ g2, const float* __restrict__ b2,
                  const float* __restrict__ fc1_b, const float* __restrict__ fc2_b,
                  float* __restrict__ xio)
{
    extern __shared__ char smem_raw[];
    __nv_bfloat16* xhi = (__nv_bfloat16*)smem_raw;
    __nv_bfloat16* xlo = xhi + 64*XLDA;
    __nv_bfloat16* hhi = xlo + 64*XLDA;
    __nv_bfloat16* hlo = hhi + 64*HLDA;
    uint32_t* hhi32 = (uint32_t*)hhi;
    uint32_t* hlo32 = (uint32_t*)hlo;

    const uint32_t smb = cvsm(smem_raw);
    const int tid   = threadIdx.x;
    const int warp  = tid >> 5, lane = tid & 31;
    const int tok0  = blockIdx.x * 64;
    const int r     = lane >> 2;
    const int c2    = (lane & 3) * 2;
    const int q     = lane & 3;
    const int nlane = lane >> 2;
    const int la15  = lane & 15;
    const int kadj  = (lane >> 4) << 3;

    // ---- LN2 -> bf16 hi/lo A matrix in smem ----
    {
        float ga = g2[lane], gb = g2[lane+32], gc = g2[lane+64];
        float ba = b2[lane], bb = b2[lane+32], bc = b2[lane+64];
        for (int t = warp; t < 64; t += 8) {
            const float* xr = xio + (size_t)(tok0+t)*96;
            float v0 = xr[lane], v1 = xr[lane+32], v2 = xr[lane+64];
            float s = v0 + v1 + v2;
            #pragma unroll
            for (int o = 16; o; o >>= 1) s += __shfl_xor_sync(0xffffffffu, s, o);
            float mean = s * (1.0f/96.0f);
            float d0 = v0-mean, d1 = v1-mean, d2 = v2-mean;
            float q2 = d0*d0 + d1*d1 + d2*d2;
            #pragma unroll
            for (int o = 16; o; o >>= 1) q2 += __shfl_xor_sync(0xffffffffu, q2, o);
            float rstd = rsqrtf(q2*(1.0f/96.0f) + 1e-5f);
            float y0 = d0*rstd*ga + ba;
            float y1 = d1*rstd*gb + bb;
            float y2 = d2*rstd*gc + bc;
            __nv_bfloat16 h0 = __float2bfloat16_rn(y0);
            __nv_bfloat16 h1 = __float2bfloat16_rn(y1);
            __nv_bfloat16 h2 = __float2bfloat16_rn(y2);
            xhi[t*XLDA + lane]      = h0;
            xhi[t*XLDA + lane + 32] = h1;
            xhi[t*XLDA + lane + 64] = h2;
            xlo[t*XLDA + lane]      = __float2bfloat16_rn(y0 - __bfloat162float(h0));
            xlo[t*XLDA + lane + 32] = __float2bfloat16_rn(y1 - __bfloat162float(h1));
            xlo[t*XLDA + lane + 64] = __float2bfloat16_rn(y2 - __bfloat162float(h2));
        }
    }
    __syncthreads();

    float acc2[6][4];
    #pragma unroll
    for (int i = 0; i < 6; ++i)
        #pragma unroll
        for (int j = 0; j < 4; ++j) acc2[i][j] = 0.f;

    const int wm1 = warp >> 2, wn1 = warp & 3;
    const int wm2 = warp >> 1, wn2 = warp & 1;

    const uint32_t aX = smb + (wm1*32 + la15)*208 + kadj*2;      // xhi; lo +13312
    const uint32_t aH = smb + 26624 + (wm2*16 + la15)*272 + kadj*2;  // hhi; lo +17408

    for (int ch = 0; ch < 3; ++ch) {
        // ---- GEMM1: x(64x96) @ W1[:, ch*128 : +128] ----
        float acc1[2][4][4];
        #pragma unroll
        for (int a = 0; a < 2; ++a)
            #pragma unroll
            for (int b = 0; b < 4; ++b)
                #pragma unroll
                for (int c = 0; c < 4; ++c) acc1[a][b][c] = 0.f;

        #pragma unroll
        for (int s = 0; s < 6; ++s) {
            uint32_t ah[2][4], al[2][4];
            ldsm4(ah[0], aX + s*32);
            ldsm4(ah[1], aX + 3328 + s*32);
            ldsm4(al[0], aX + 13312 + s*32);
            ldsm4(al[1], aX + 13312 + 3328 + s*32);
            #pragma unroll
            for (int nt = 0; nt < 4; ++nt) {
                int n = ch*128 + wn1*32 + nt*8 + nlane;
                uint4 B = g_W1p[(s*384 + n)*4 + q];
                #pragma unroll
                for (int mt = 0; mt < 2; ++mt) {
                    mma16816(acc1[mt][nt], ah[mt], B.x, B.y);
                    mma16816(acc1[mt][nt], ah[mt], B.z, B.w);
                    mma16816(acc1[mt][nt], al[mt], B.x, B.y);
                }
            }
        }

        __syncthreads();   // previous chunk's GEMM2 reads of h are done

        // ---- bias + exact GELU + bf16 split -> h smem ----
        #pragma unroll
        for (int mt = 0; mt < 2; ++mt) {
            int row0 = wm1*32 + mt*16 + r;
            #pragma unroll
            for (int nt = 0; nt < 4; ++nt) {
                int cc = wn1*32 + nt*8 + c2;
                float2 bia = *(const float2*)(fc1_b + ch*128 + cc);
                float g00 = gelu_exact(acc1[mt][nt][0] + bia.x);
                float g01 = gelu_exact(acc1[mt][nt][1] + bia.y);
                uint32_t hp, lp;
                split2(g00, g01, hp, lp);
                hhi32[(row0*HLDA + cc) >> 1] = hp;
                hlo32[(row0*HLDA + cc) >> 1] = lp;
                float g10 = gelu_exact(acc1[mt][nt][2] + bia.x);
                float g11 = gelu_exact(acc1[mt][nt][3] + bia.y);
                split2(g10, g11, hp, lp);
                hhi32[((row0+8)*HLDA + cc) >> 1] = hp;
                hlo32[((row0+8)*HLDA + cc) >> 1] = lp;
            }
        }
        __syncthreads();

        // ---- GEMM2 partial: acc2 += h_chunk(64x128) @ W2[chunk, :] ----
        #pragma unroll
        for (int s = 0; s < 8; ++s) {
            uint32_t ah[4], al[4];
            ldsm4(ah, aH + s*32);
            ldsm4(al, aH + 17408 + s*32);
            const int S = ch*8 + s;
            #pragma unroll
            for (int nt = 0; nt < 6; ++nt) {
                int n = wn2*48 + nt*8 + nlane;
                uint4 B = g_W2p[(S*96 + n)*4 + q];
                mma16816(acc2[nt], ah, B.x, B.y);
                mma16816(acc2[nt], ah, B.z, B.w);
                mma16816(acc2[nt], al, B.x, B.y);
            }
        }
    }

    // ---- epilogue: bias + residual, in place ----
    {
        const int m0 = wm2*16;
        #pragma unroll
        for (int nt = 0; nt < 6; ++nt) {
            int cg = wn2*48 + nt*8 + c2;
            float2 bia = *(const float2*)(fc2_b + cg);
            size_t b0 = (size_t)(tok0 + m0 + r)*96 + cg;
            float2 sk0 = *(const float2*)(xio + b0);
            float2 o0;
            o0.x = acc2[nt][0] + bia.x + sk0.x;
            o0.y = acc2[nt][1] + bia.y + sk0.y;
            *(float2*)(xio + b0) = o0;
            size_t b1 = b0 + (size_t)8*96;
            float2 sk1 = *(const float2*)(xio + b1);
            float2 o1;
            o1.x = acc2[nt][2] + bia.x + sk1.x;
            o1.y = acc2[nt][3] + bia.y + sk1.y;
            *(float2*)(xio + b1) = o1;
        }
    }
}

// ---------------------------------------------------------------------------
extern "C" void kernel_launch(void* const* d_in, const int* in_sizes, int n_in,
                              void* d_out, int out_size)
{
    const float* x      = (const float*)d_in[0];
    const float* g1     = (const float*)d_in[1];
    const float* b1     = (const float*)d_in[2];
    const float* qkv_w  = (const float*)d_in[3];
    const float* qkv_b  = (const float*)d_in[4];
    const float* proj_w = (const float*)d_in[5];
    const float* proj_b = (const float*)d_in[6];
    const float* rpb    = (const float*)d_in[7];
    const float* g2     = (const float*)d_in[8];
    const float* b2     = (const float*)d_in[9];
    const float* fc1_w  = (const float*)d_in[10];
    const float* fc1_b  = (const float*)d_in[11];
    const float* fc2_w  = (const float*)d_in[12];
    const float* fc2_b  = (const float*)d_in[13];
    const int*   relidx = (const int*)d_in[14];
    const float* amask  = (const float*)d_in[15];
    float* out = (float*)d_out;

    const int smem1 = 109824;
    const int smem2 = (2*64*XLDA + 2*64*HLDA)*(int)sizeof(__nv_bfloat16);
    cudaFuncSetAttribute(swin_attn_mma, cudaFuncAttributeMaxDynamicSharedMemorySize, smem1);
    cudaFuncSetAttribute(swin_mlp_mma,  cudaFuncAttributeMaxDynamicSharedMemorySize, smem2);

    pack_weights<<<36, 256>>>(fc1_w, fc2_w, qkv_w, proj_w);
    build_bias_mask<<<12288, 256>>>(rpb, relidx, amask);
    swin_attn_mma<<<NWIN_TOT, 256, smem1>>>(x, g1, b1, qkv_b, proj_b, out);
    swin_mlp_mma<<<NBLK2, 256, smem2>>>(g2, b2, fc1_b, fc2_b, out);
}

// round 5
// speedup vs baseline: 4.0661x; 1.0325x over previous
#include <cuda_runtime.h>
#include <cuda_bf16.h>
#include <math.h>
#include <stdint.h>

// Problem constants
#define HH      112
#define WW2     112
#define CC      96
#define SHIFT_  3
#define NTOK    49
#define QKSCALE 0.17677669529663687f
#define NWIN_TOT 16384
#define NBLK2    12544     // 802816 / 64

// ===========================================================================
// MMA / LDSM helpers
// ===========================================================================
__device__ __forceinline__ void mma16816(float d[4], const uint32_t a[4],
                                         uint32_t b0, uint32_t b1) {
    asm volatile(
        "mma.sync.aligned.m16n8k16.row.col.f32.bf16.bf16.f32 "
        "{%0,%1,%2,%3},{%4,%5,%6,%7},{%8,%9},{%0,%1,%2,%3};"
        : "+f"(d[0]), "+f"(d[1]), "+f"(d[2]), "+f"(d[3])
        : "r"(a[0]), "r"(a[1]), "r"(a[2]), "r"(a[3]), "r"(b0), "r"(b1));
}

__device__ __forceinline__ void ldsm4(uint32_t r[4], uint32_t saddr) {
    asm volatile("ldmatrix.sync.aligned.m8n8.x4.shared.b16 {%0,%1,%2,%3}, [%4];"
        : "=r"(r[0]), "=r"(r[1]), "=r"(r[2]), "=r"(r[3]) : "r"(saddr));
}

__device__ __forceinline__ void ldsm4t(uint32_t r[4], uint32_t saddr) {
    asm volatile("ldmatrix.sync.aligned.m8n8.x4.trans.shared.b16 {%0,%1,%2,%3}, [%4];"
        : "=r"(r[0]), "=r"(r[1]), "=r"(r[2]), "=r"(r[3]) : "r"(saddr));
}

__device__ __forceinline__ uint32_t cvsm(const void* p) {
    return (uint32_t)__cvta_generic_to_shared(p);
}

__device__ __forceinline__ uint32_t packbf(float x0, float x1) {
    uint32_t p;
    asm("cvt.rn.bf16x2.f32 %0, %1, %2;" : "=r"(p) : "f"(x1), "f"(x0));
    return p;
}

__device__ __forceinline__ void split2(float x0, float x1,
                                       uint32_t& hi, uint32_t& lo) {
    uint32_t hp = packbf(x0, x1);
    __nv_bfloat162 hb = *reinterpret_cast<__nv_bfloat162*>(&hp);
    float l0 = x0 - __bfloat162float(hb.x);
    float l1 = x1 - __bfloat162float(hb.y);
    hi = hp; lo = packbf(l0, l1);
}

__device__ __forceinline__ float gelu_exact(float v) {
    return 0.5f * v * (1.0f + erff(v * 0.7071067811865476f));
}

// Pre-packed weights: [k16step s][n][q] -> uint4 (bh0, bh1, bl0, bl1)
__device__ uint4 g_W1p[6 * 384 * 4];
__device__ uint4 g_W2p[24 * 96 * 4];
__device__ uint4 g_Wqp[6 * 288 * 4];
__device__ uint4 g_Wpp[6 * 96 * 4];
// fused rel-pos-bias + shift mask, padded to 64x64 with -1e4: [rem][h][i][j]
__device__ float g_bm[256 * 3 * 64 * 64];

__global__ void pack_weights(const float* __restrict__ fc1_w,
                             const float* __restrict__ fc2_w,
                             const float* __restrict__ qkv_w,
                             const float* __restrict__ proj_w) {
    int idx = blockIdx.x * 256 + threadIdx.x;
    if (idx >= 9216) return;
    uint32_t h0, l0, h1, l1;
    {   // fc1: 96 x 384 -> 6*384*4 = 9216 entries
        int q = idx & 3, n = (idx >> 2) % 384, s = idx / 1536;
        int k = s * 16 + 2 * q;
        split2(fc1_w[k * 384 + n],       fc1_w[(k + 1) * 384 + n], h0, l0);
        split2(fc1_w[(k + 8) * 384 + n], fc1_w[(k + 9) * 384 + n], h1, l1);
        g_W1p[idx] = make_uint4(h0, h1, l0, l1);
    }
    {   // fc2: 384 x 96 -> 24*96*4 = 9216 entries
        int q = idx & 3, n = (idx >> 2) % 96, s = idx / 384;
        int k = s * 16 + 2 * q;
        split2(fc2_w[k * 96 + n],       fc2_w[(k + 1) * 96 + n], h0, l0);
        split2(fc2_w[(k + 8) * 96 + n], fc2_w[(k + 9) * 96 + n], h1, l1);
        g_W2p[idx] = make_uint4(h0, h1, l0, l1);
    }
    if (idx < 6912) {   // qkv: 96 x 288 (q cols pre-scaled)
        int q = idx & 3, n = (idx >> 2) % 288, s = idx / 1152;
        int k = s * 16 + 2 * q;
        float sc = (n < 96) ? QKSCALE : 1.0f;
        split2(qkv_w[k * 288 + n] * sc,       qkv_w[(k + 1) * 288 + n] * sc, h0, l0);
        split2(qkv_w[(k + 8) * 288 + n] * sc, qkv_w[(k + 9) * 288 + n] * sc, h1, l1);
        g_Wqp[idx] = make_uint4(h0, h1, l0, l1);
    }
    if (idx < 2304) {   // proj: 96 x 96
        int q = idx & 3, n = (idx >> 2) % 96, s = idx / 384;
        int k = s * 16 + 2 * q;
        split2(proj_w[k * 96 + n],       proj_w[(k + 1) * 96 + n], h0, l0);
        split2(proj_w[(k + 8) * 96 + n], proj_w[(k + 9) * 96 + n], h1, l1);
        g_Wpp[idx] = make_uint4(h0, h1, l0, l1);
    }
}

__global__ void build_bias_mask(const float* __restrict__ rpb,
                                const int* __restrict__ relidx,
                                const float* __restrict__ amask) {
    int idx = blockIdx.x * 256 + threadIdx.x;
    int j = idx & 63, i = (idx >> 6) & 63;
    int h = (idx >> 12) % 3;
    int rem = idx / 12288;
    float v = -10000.0f;
    if (i < NTOK && j < NTOK)
        v = rpb[relidx[i * NTOK + j] * 3 + h] + amask[(size_t)rem * 2401 + i * NTOK + j];
    g_bm[idx] = v;
}

// ---------------------------------------------------------------------------
// Kernel 1: LN1 + shifted-window MHSA + proj + residual, tensor cores + LDSM.
// One block per window (49 tokens -> 64), 256 threads (8 warps).
// smem bytes:
//   [0, 27648)        xlnHi[64][104] + xlnLo[64][104]
//   [27648, 40960)    qHi[64][104]   -> later aoHi
//   [40960, 54272)    kHi[64][104]   -> later aoLo
//   [54272, 67584)    vHi[64][104]   (token-major)
//   [67584, 80896)    vLo[64][104]
//   [80896, 108544)   probsHi[3][64][72]
//   [108544, 108740)  srcI[49]
// ---------------------------------------------------------------------------
__global__ __launch_bounds__(256, 2)
void swin_attn_mma(const float* __restrict__ x,
                   const float* __restrict__ g1, const float* __restrict__ b1,
                   const float* __restrict__ qkv_b,
                   const float* __restrict__ proj_b,
                   float* __restrict__ out)
{
    extern __shared__ char sm[];
    __nv_bfloat16* xlnHi = (__nv_bfloat16*)(sm);
    __nv_bfloat16* xlnLo = (__nv_bfloat16*)(sm + 13312);
    uint32_t* qh32 = (uint32_t*)(sm + 27648);
    uint32_t* kh32 = (uint32_t*)(sm + 40960);
    uint32_t* vh32 = (uint32_t*)(sm + 54272);
    uint32_t* vl32 = (uint32_t*)(sm + 67584);
    uint32_t* ph32 = (uint32_t*)(sm + 80896);
    uint32_t* aoh32 = qh32;                     // alias q
    uint32_t* aol32 = kh32;                     // alias k
    int* srcI = (int*)(sm + 108544);

    const uint32_t smb = cvsm(sm);
    const int tid  = threadIdx.x;
    const int warp = tid >> 5, lane = tid & 31;
    const int r    = lane >> 2;
    const int qd   = lane & 3;
    const int c2   = qd * 2;
    const int la15 = lane & 15;               // A-fragment row adj
    const int kadj = (lane >> 4) << 3;        // A-fragment k adj
    const int lbn  = (lane & 7) | ((lane >> 4) << 3);   // B n adj (non-trans)
    const int kbdj = ((lane >> 3) & 1) << 3;            // B k adj (non-trans)
    const int w    = blockIdx.x;
    const int bimg = w >> 8;
    const int rem  = w & 255;
    const int wh   = rem >> 4, wwc = rem & 15;

    // ---- Phase 0: LN + shifted gather -> xln hi/lo bf16 ----
    {
        float ga = g1[lane], gb = g1[lane+32], gc = g1[lane+64];
        float ba = b1[lane], bb = b1[lane+32], bc = b1[lane+64];
        for (int t = warp; t < NTOK; t += 8) {
            int ii = t / 7, jj = t - ii*7;
            int oh = wh*7 + ii + SHIFT_; if (oh >= HH)  oh -= HH;
            int ow = wwc*7 + jj + SHIFT_; if (ow >= WW2) ow -= WW2;
            int src = (bimg*HH + oh)*WW2 + ow;
            if (lane == 0) srcI[t] = src;
            const float* xr = x + (size_t)src*CC;
            float v0 = xr[lane], v1 = xr[lane+32], v2 = xr[lane+64];
            float s = v0 + v1 + v2;
            #pragma unroll
            for (int o = 16; o; o >>= 1) s += __shfl_xor_sync(0xffffffffu, s, o);
            float mean = s * (1.0f/96.0f);
            float d0 = v0-mean, d1 = v1-mean, d2 = v2-mean;
            float q2 = d0*d0 + d1*d1 + d2*d2;
            #pragma unroll
            for (int o = 16; o; o >>= 1) q2 += __shfl_xor_sync(0xffffffffu, q2, o);
            float rstd = rsqrtf(q2*(1.0f/96.0f) + 1e-5f);
            float y0 = d0*rstd*ga + ba, y1 = d1*rstd*gb + bb, y2 = d2*rstd*gc + bc;
            __nv_bfloat16 h0 = __float2bfloat16_rn(y0);
            __nv_bfloat16 h1 = __float2bfloat16_rn(y1);
            __nv_bfloat16 h2 = __float2bfloat16_rn(y2);
            xlnHi[t*104 + lane]    = h0;
            xlnHi[t*104 + lane+32] = h1;
            xlnHi[t*104 + lane+64] = h2;
            xlnLo[t*104 + lane]    = __float2bfloat16_rn(y0 - __bfloat162float(h0));
            xlnLo[t*104 + lane+32] = __float2bfloat16_rn(y1 - __bfloat162float(h1));
            xlnLo[t*104 + lane+64] = __float2bfloat16_rn(y2 - __bfloat162float(h2));
        }
        __nv_bfloat16 z = __float2bfloat16_rn(0.0f);
        for (int idx = tid; idx < 15*96; idx += 256) {
            int rr = NTOK + idx/96, cc = idx - (idx/96)*96;
            xlnHi[rr*104 + cc] = z;
            xlnLo[rr*104 + cc] = z;
        }
    }
    __syncthreads();

    // ---- Phase 1: QKV GEMM (M=64, K=96, N=288), split 3-MMA ----
    {
        const int wm = warp >> 2, wn = warp & 3;
        const uint32_t aHi = smb + (wm*32 + la15)*208 + kadj*2;
        const uint32_t aLo = aHi + 13312;
        for (int g = 0; g < 3; ++g) {
            float acc[3][2][4];
            #pragma unroll
            for (int a = 0; a < 3; ++a)
                #pragma unroll
                for (int b = 0; b < 2; ++b)
                    #pragma unroll
                    for (int c = 0; c < 4; ++c) acc[a][b][c] = 0.f;
            #pragma unroll
            for (int s = 0; s < 6; ++s) {
                uint32_t ah[2][4], al[2][4];
                ldsm4(ah[0], aHi + s*32);
                ldsm4(ah[1], aHi + 3328 + s*32);
                ldsm4(al[0], aLo + s*32);
                ldsm4(al[1], aLo + 3328 + s*32);
                #pragma unroll
                for (int nt = 0; nt < 3; ++nt) {
                    int n = wn*72 + g*24 + nt*8 + r;
                    uint4 B = g_Wqp[(s*288 + n)*4 + qd];
                    #pragma unroll
                    for (int mt = 0; mt < 2; ++mt) {
                        mma16816(acc[nt][mt], ah[mt], B.x, B.y);
                        mma16816(acc[nt][mt], ah[mt], B.z, B.w);
                        mma16816(acc[nt][mt], al[mt], B.x, B.y);
                    }
                }
            }
            // epilogue: +bias, route to qHi / kHi / v token-major hi+lo
            #pragma unroll
            for (int nt = 0; nt < 3; ++nt) {
                int nb = wn*72 + g*24 + nt*8 + c2;
                float b0v = qkv_b[nb], b1v = qkv_b[nb+1];
                if (nb < 96) { b0v *= QKSCALE; b1v *= QKSCALE; }
                #pragma unroll
                for (int mt = 0; mt < 2; ++mt) {
                    int row = wm*32 + mt*16 + r;
                    float v00 = acc[nt][mt][0] + b0v, v01 = acc[nt][mt][1] + b1v;
                    float v10 = acc[nt][mt][2] + b0v, v11 = acc[nt][mt][3] + b1v;
                    if (nb < 96) {
                        qh32[(row*104 + nb) >> 1]     = packbf(v00, v01);
                        qh32[((row+8)*104 + nb) >> 1] = packbf(v10, v11);
                    } else if (nb < 192) {
                        int c = nb - 96;
                        kh32[(row*104 + c) >> 1]      = packbf(v00, v01);
                        kh32[((row+8)*104 + c) >> 1]  = packbf(v10, v11);
                    } else {
                        int c = nb - 192;
                        uint32_t hp, lp;
                        split2(v00, v01, hp, lp);
                        vh32[(row*104 + c) >> 1] = hp;
                        vl32[(row*104 + c) >> 1] = lp;
                        split2(v10, v11, hp, lp);
                        vh32[((row+8)*104 + c) >> 1] = hp;
                        vl32[((row+8)*104 + c) >> 1] = lp;
                    }
                }
            }
        }
    }
    __syncthreads();

    // ---- Phase 2: scores (QK^T) + fused bias/mask + in-reg softmax ----
    for (int u = warp; u < 12; u += 8) {
        int h = u >> 2, mt = u & 3;
        int rowb = mt * 16;
        uint32_t a[4];
        ldsm4(a, smb + 27648 + (rowb + la15)*208 + (h*32 + kadj)*2);
        float acc[8][4];
        #pragma unroll
        for (int aa = 0; aa < 8; ++aa)
            #pragma unroll
            for (int c = 0; c < 4; ++c) acc[aa][c] = 0.f;
        const uint32_t kb = smb + 40960 + lbn*208 + (h*32 + kbdj)*2;
        #pragma unroll
        for (int p = 0; p < 4; ++p) {
            uint32_t b[4];
            ldsm4(b, kb + p*16*208);
            mma16816(acc[2*p],   a, b[0], b[1]);
            mma16816(acc[2*p+1], a, b[2], b[3]);
        }
        // fused bias+mask, softmax across row (4 lanes per row)
        const float* bmb = g_bm + ((size_t)(rem*3 + h)) * 4096;
        int i0 = rowb + r, i1 = i0 + 8;
        float m0 = -1e30f, m1 = -1e30f;
        #pragma unroll
        for (int nt = 0; nt < 8; ++nt) {
            int j = nt*8 + c2;
            float2 bm0 = *(const float2*)(bmb + i0*64 + j);
            float2 bm1 = *(const float2*)(bmb + i1*64 + j);
            acc[nt][0] += bm0.x; acc[nt][1] += bm0.y;
            acc[nt][2] += bm1.x; acc[nt][3] += bm1.y;
            m0 = fmaxf(m0, fmaxf(acc[nt][0], acc[nt][1]));
            m1 = fmaxf(m1, fmaxf(acc[nt][2], acc[nt][3]));
        }
        m0 = fmaxf(m0, __shfl_xor_sync(0xffffffffu, m0, 1));
        m0 = fmaxf(m0, __shfl_xor_sync(0xffffffffu, m0, 2));
        m1 = fmaxf(m1, __shfl_xor_sync(0xffffffffu, m1, 1));
        m1 = fmaxf(m1, __shfl_xor_sync(0xffffffffu, m1, 2));
        float s0 = 0.f, s1 = 0.f;
        #pragma unroll
        for (int nt = 0; nt < 8; ++nt) {
            acc[nt][0] = __expf(acc[nt][0] - m0);
            acc[nt][1] = __expf(acc[nt][1] - m0);
            acc[nt][2] = __expf(acc[nt][2] - m1);
            acc[nt][3] = __expf(acc[nt][3] - m1);
            s0 += acc[nt][0] + acc[nt][1];
            s1 += acc[nt][2] + acc[nt][3];
        }
        s0 += __shfl_xor_sync(0xffffffffu, s0, 1);
        s0 += __shfl_xor_sync(0xffffffffu, s0, 2);
        s1 += __shfl_xor_sync(0xffffffffu, s1, 1);
        s1 += __shfl_xor_sync(0xffffffffu, s1, 2);
        float inv0 = 1.0f / s0, inv1 = 1.0f / s1;
        #pragma unroll
        for (int nt = 0; nt < 8; ++nt) {
            ph32[(h*64 + i0)*36 + nt*4 + qd] = packbf(acc[nt][0]*inv0, acc[nt][1]*inv0);
            ph32[(h*64 + i1)*36 + nt*4 + qd] = packbf(acc[nt][2]*inv1, acc[nt][3]*inv1);
        }
    }
    __syncthreads();

    // ---- Phase 3: A.V -> attn_out hi/lo (alias q/k); V via trans-LDSM ----
    {
        const int wm2 = warp >> 1, wn2 = warp & 1;
        const int hA = wn2, hB = wn2 + 1;
        float acc[6][4];
        #pragma unroll
        for (int a = 0; a < 6; ++a)
            #pragma unroll
            for (int c = 0; c < 4; ++c) acc[a][c] = 0.f;
        const uint32_t pA_b = smb + 80896 + (hA*64 + wm2*16 + la15)*144 + kadj*2;
        const uint32_t pB_b = smb + 80896 + (hB*64 + wm2*16 + la15)*144 + kadj*2;
        const uint32_t v_b  = smb + 54272 + la15*208 + (wn2*48 + kadj)*2;
        #pragma unroll
        for (int ks = 0; ks < 4; ++ks) {
            uint32_t pAh[4], pBh[4];
            ldsm4(pAh, pA_b + ks*32);
            ldsm4(pBh, pB_b + ks*32);
            #pragma unroll
            for (int pp = 0; pp < 3; ++pp) {
                uint32_t bh[4], bl[4];
                uint32_t va = v_b + ks*16*208 + pp*32;
                ldsm4t(bh, va);
                ldsm4t(bl, va + 13312);
                bool useA = (((wn2*48 + pp*16) >> 5) == hA);
                const uint32_t* ph_ = useA ? pAh : pBh;
                mma16816(acc[2*pp],   ph_, bh[0], bh[1]);
                mma16816(acc[2*pp],   ph_, bl[0], bl[1]);
                mma16816(acc[2*pp+1], ph_, bh[2], bh[3]);
                mma16816(acc[2*pp+1], ph_, bl[2], bl[3]);
            }
        }
        #pragma unroll
        for (int nt = 0; nt < 6; ++nt) {
            int c = wn2*48 + nt*8 + c2;
            int i0 = wm2*16 + r;
            uint32_t hp, lp;
            split2(acc[nt][0], acc[nt][1], hp, lp);
            aoh32[(i0*104 + c) >> 1] = hp;
            aol32[(i0*104 + c) >> 1] = lp;
            split2(acc[nt][2], acc[nt][3], hp, lp);
            aoh32[((i0+8)*104 + c) >> 1] = hp;
            aol32[((i0+8)*104 + c) >> 1] = lp;
        }
    }
    __syncthreads();

    // ---- Phase 4: proj (split 3-MMA) + bias + residual -> gmem ----
    {
        const int wm = warp >> 2, wn = warp & 3;
        const uint32_t aHi = smb + 27648 + (wm*32 + la15)*208 + kadj*2;
        const uint32_t aLo = aHi + 13312;
        float acc[3][2][4];
        #pragma unroll
        for (int a = 0; a < 3; ++a)
            #pragma unroll
            for (int b = 0; b < 2; ++b)
                #pragma unroll
                for (int c = 0; c < 4; ++c) acc[a][b][c] = 0.f;
        #pragma unroll
        for (int s = 0; s < 6; ++s) {
            uint32_t ah[2][4], al[2][4];
            ldsm4(ah[0], aHi + s*32);
            ldsm4(ah[1], aHi + 3328 + s*32);
            ldsm4(al[0], aLo + s*32);
            ldsm4(al[1], aLo + 3328 + s*32);
            #pragma unroll
            for (int nt = 0; nt < 3; ++nt) {
                int n = wn*24 + nt*8 + r;
                uint4 B = g_Wpp[(s*96 + n)*4 + qd];
                #pragma unroll
                for (int mt = 0; mt < 2; ++mt) {
                    mma16816(acc[nt][mt], ah[mt], B.x, B.y);
                    mma16816(acc[nt][mt], ah[mt], B.z, B.w);
                    mma16816(acc[nt][mt], al[mt], B.x, B.y);
                }
            }
        }
        #pragma unroll
        for (int nt = 0; nt < 3; ++nt) {
            int c = wn*24 + nt*8 + c2;
            float2 pb = *(const float2*)(proj_b + c);
            #pragma unroll
            for (int mt = 0; mt < 2; ++mt) {
                int i0 = wm*32 + mt*16 + r;
                if (i0 < NTOK) {
                    size_t base = (size_t)srcI[i0]*96 + c;
                    float2 xr = *(const float2*)(x + base);
                    float2 o;
                    o.x = acc[nt][mt][0] + pb.x + xr.x;
                    o.y = acc[nt][mt][1] + pb.y + xr.y;
                    *(float2*)(out + base) = o;
                }
                int i1 = i0 + 8;
                if (i1 < NTOK) {
                    size_t base = (size_t)srcI[i1]*96 + c;
                    float2 xr = *(const float2*)(x + base);
                    float2 o;
                    o.x = acc[nt][mt][2] + pb.x + xr.x;
                    o.y = acc[nt][mt][3] + pb.y + xr.y;
                    *(float2*)(out + base) = o;
                }
            }
        }
    }
}

// ---------------------------------------------------------------------------
// Kernel 2: LN2 + MLP via bf16 split tensor-core MMA + LDSM (unchanged).
// ---------------------------------------------------------------------------
#define XLDA 104
#define HLDA 136

__global__ __launch_bounds__(256, 2)
void swin_mlp_mma(const float* __restrict__ g2, const float* __restrict__ b2,
                  const float* __restrict__ fc1_b, const float* __restrict__ fc2_b,
                  float* __restrict__ xio)
{
    extern __shared__ char smem_raw[];
    __nv_bfloat16* xhi = (__nv_bfloat16*)smem_raw;
    __nv_bfloat16* xlo = xhi + 64*XLDA;
    __nv_bfloat16* hhi = xlo + 64*XLDA;
    __nv_bfloat16* hlo = hhi + 64*HLDA;
    uint32_t* hhi32 = (uint32_t*)hhi;
    uint32_t* hlo32 = (uint32_t*)hlo;

    const uint32_t smb = cvsm(smem_raw);
    const int tid   = threadIdx.x;
    const int warp  = tid >> 5, lane = tid & 31;
    const int tok0  = blockIdx.x * 64;
    const int r     = lane >> 2;
    const int c2    = (lane & 3) * 2;
    const int q     = lane & 3;
    const int nlane = lane >> 2;
    const int la15  = lane & 15;
    const int kadj  = (lane >> 4) << 3;

    // ---- LN2 -> bf16 hi/lo A matrix in smem ----
    {
        float ga = g2[lane], gb = g2[lane+32], gc = g2[lane+64];
        float ba = b2[lane], bb = b2[lane+32], bc = b2[lane+64];
        for (int t = warp; t < 64; t += 8) {
            const float* xr = xio + (size_t)(tok0+t)*96;
            float v0 = xr[lane], v1 = xr[lane+32], v2 = xr[lane+64];
            float s = v0 + v1 + v2;
            #pragma unroll
            for (int o = 16; o; o >>= 1) s += __shfl_xor_sync(0xffffffffu, s, o);
            float mean = s * (1.0f/96.0f);
            float d0 = v0-mean, d1 = v1-mean, d2 = v2-mean;
            float q2 = d0*d0 + d1*d1 + d2*d2;
            #pragma unroll
            for (int o = 16; o; o >>= 1) q2 += __shfl_xor_sync(0xffffffffu, q2, o);
            float rstd = rsqrtf(q2*(1.0f/96.0f) + 1e-5f);
            float y0 = d0*rstd*ga + ba;
            float y1 = d1*rstd*gb + bb;
            float y2 = d2*rstd*gc + bc;
            __nv_bfloat16 h0 = __float2bfloat16_rn(y0);
            __nv_bfloat16 h1 = __float2bfloat16_rn(y1);
            __nv_bfloat16 h2 = __float2bfloat16_rn(y2);
            xhi[t*XLDA + lane]      = h0;
            xhi[t*XLDA + lane + 32] = h1;
            xhi[t*XLDA + lane + 64] = h2;
            xlo[t*XLDA + lane]      = __float2bfloat16_rn(y0 - __bfloat162float(h0));
            xlo[t*XLDA + lane + 32] = __float2bfloat16_rn(y1 - __bfloat162float(h1));
            xlo[t*XLDA + lane + 64] = __float2bfloat16_rn(y2 - __bfloat162float(h2));
        }
    }
    __syncthreads();

    float acc2[6][4];
    #pragma unroll
    for (int i = 0; i < 6; ++i)
        #pragma unroll
        for (int j = 0; j < 4; ++j) acc2[i][j] = 0.f;

    const int wm1 = warp >> 2, wn1 = warp & 3;
    const int wm2 = warp >> 1, wn2 = warp & 1;

    const uint32_t aX = smb + (wm1*32 + la15)*208 + kadj*2;
    const uint32_t aH = smb + 26624 + (wm2*16 + la15)*272 + kadj*2;

    for (int ch = 0; ch < 3; ++ch) {
        float acc1[2][4][4];
        #pragma unroll
        for (int a = 0; a < 2; ++a)
            #pragma unroll
            for (int b = 0; b < 4; ++b)
                #pragma unroll
                for (int c = 0; c < 4; ++c) acc1[a][b][c] = 0.f;

        #pragma unroll
        for (int s = 0; s < 6; ++s) {
            uint32_t ah[2][4], al[2][4];
            ldsm4(ah[0], aX + s*32);
            ldsm4(ah[1], aX + 3328 + s*32);
            ldsm4(al[0], aX + 13312 + s*32);
            ldsm4(al[1], aX + 13312 + 3328 + s*32);
            #pragma unroll
            for (int nt = 0; nt < 4; ++nt) {
                int n = ch*128 + wn1*32 + nt*8 + nlane;
                uint4 B = g_W1p[(s*384 + n)*4 + q];
                #pragma unroll
                for (int mt = 0; mt < 2; ++mt) {
                    mma16816(acc1[mt][nt], ah[mt], B.x, B.y);
                    mma16816(acc1[mt][nt], ah[mt], B.z, B.w);
                    mma16816(acc1[mt][nt], al[mt], B.x, B.y);
                }
            }
        }

        __syncthreads();

        #pragma unroll
        for (int mt = 0; mt < 2; ++mt) {
            int row0 = wm1*32 + mt*16 + r;
            #pragma unroll
            for (int nt = 0; nt < 4; ++nt) {
                int cc = wn1*32 + nt*8 + c2;
                float2 bia = *(const float2*)(fc1_b + ch*128 + cc);
                float g00 = gelu_exact(acc1[mt][nt][0] + bia.x);
                float g01 = gelu_exact(acc1[mt][nt][1] + bia.y);
                uint32_t hp, lp;
                split2(g00, g01, hp, lp);
                hhi32[(row0*HLDA + cc) >> 1] = hp;
                hlo32[(row0*HLDA + cc) >> 1] = lp;
                float g10 = gelu_exact(acc1[mt][nt][2] + bia.x);
                float g11 = gelu_exact(acc1[mt][nt][3] + bia.y);
                split2(g10, g11, hp, lp);
                hhi32[((row0+8)*HLDA + cc) >> 1] = hp;
                hlo32[((row0+8)*HLDA + cc) >> 1] = lp;
            }
        }
        __syncthreads();

        #pragma unroll
        for (int s = 0; s < 8; ++s) {
            uint32_t ah[4], al[4];
            ldsm4(ah, aH + s*32);
            ldsm4(al, aH + 17408 + s*32);
            const int S = ch*8 + s;
            #pragma unroll
            for (int nt = 0; nt < 6; ++nt) {
                int n = wn2*48 + nt*8 + nlane;
                uint4 B = g_W2p[(S*96 + n)*4 + q];
                mma16816(acc2[nt], ah, B.x, B.y);
                mma16816(acc2[nt], ah, B.z, B.w);
                mma16816(acc2[nt], al, B.x, B.y);
            }
        }
    }

    {
        const int m0 = wm2*16;
        #pragma unroll
        for (int nt = 0; nt < 6; ++nt) {
            int cg = wn2*48 + nt*8 + c2;
            float2 bia = *(const float2*)(fc2_b + cg);
            size_t b0 = (size_t)(tok0 + m0 + r)*96 + cg;
            float2 sk0 = *(const float2*)(xio + b0);
            float2 o0;
            o0.x = acc2[nt][0] + bia.x + sk0.x;
            o0.y = acc2[nt][1] + bia.y + sk0.y;
            *(float2*)(xio + b0) = o0;
            size_t b1 = b0 + (size_t)8*96;
            float2 sk1 = *(const float2*)(xio + b1);
            float2 o1;
            o1.x = acc2[nt][2] + bia.x + sk1.x;
            o1.y = acc2[nt][3] + bia.y + sk1.y;
            *(float2*)(xio + b1) = o1;
        }
    }
}

// ---------------------------------------------------------------------------
extern "C" void kernel_launch(void* const* d_in, const int* in_sizes, int n_in,
                              void* d_out, int out_size)
{
    const float* x      = (const float*)d_in[0];
    const float* g1     = (const float*)d_in[1];
    const float* b1     = (const float*)d_in[2];
    const float* qkv_w  = (const float*)d_in[3];
    const float* qkv_b  = (const float*)d_in[4];
    const float* proj_w = (const float*)d_in[5];
    const float* proj_b = (const float*)d_in[6];
    const float* rpb    = (const float*)d_in[7];
    const float* g2     = (const float*)d_in[8];
    const float* b2     = (const float*)d_in[9];
    const float* fc1_w  = (const float*)d_in[10];
    const float* fc1_b  = (const float*)d_in[11];
    const float* fc2_w  = (const float*)d_in[12];
    const float* fc2_b  = (const float*)d_in[13];
    const int*   relidx = (const int*)d_in[14];
    const float* amask  = (const float*)d_in[15];
    float* out = (float*)d_out;

    const int smem1 = 108800;
    const int smem2 = (2*64*XLDA + 2*64*HLDA)*(int)sizeof(__nv_bfloat16);
    cudaFuncSetAttribute(swin_attn_mma, cudaFuncAttributeMaxDynamicSharedMemorySize, smem1);
    cudaFuncSetAttribute(swin_mlp_mma,  cudaFuncAttributeMaxDynamicSharedMemorySize, smem2);

    pack_weights<<<36, 256>>>(fc1_w, fc2_w, qkv_w, proj_w);
    build_bias_mask<<<12288, 256>>>(rpb, relidx, amask);
    swin_attn_mma<<<NWIN_TOT, 256, smem1>>>(x, g1, b1, qkv_b, proj_b, out);
    swin_mlp_mma<<<NBLK2, 256, smem2>>>(g2, b2, fc1_b, fc2_b, out);
}